// round 12
// baseline (speedup 1.0000x reference)
#include <cuda_runtime.h>
#include <cuda_bf16.h>
#include <math.h>
#include <stdint.h>

#define HW 16384   // 128x128 BEV
#define NCAM 6

// ---------------- scratch (static device allocations; no cudaMalloc) ----------------
__device__ float g_ftr[22440 * 128];        // feats transposed channel-last, all levels
__device__ float g_col[1152 * 16384];       // im2col h/l bf16 planes (reused both convs)
__device__ float g_y[128 * 16384];          // pre-norm accumulator (reused)
__device__ float g_q1[128 * 16384];
__device__ float g_q2[128 * 16384];
__device__ float g_pts[16384 * 24];
__device__ float g_swm[16384 * 32];
__device__ float g_asf[1024 * 16384];       // h/l bf16 planes
__device__ float g_m1[512 * 16384];         // h/l bf16 planes
__device__ float g_m2[512 * 16384];         // h/l bf16 planes
__device__ uint16_t g_wsp[2 * 1146880];     // pre-split weights (h plane, then l plane)

// ---------------- helpers ----------------
__device__ __forceinline__ float gelu_exact(float x) { return x * normcdff(x); }

__device__ __forceinline__ uint32_t smem_to_u32(const void* p) {
    uint32_t a;
    asm("{ .reg .u64 t; cvta.to.shared.u64 t, %1; cvt.u32.u64 %0, t; }" : "=r"(a) : "l"(p));
    return a;
}

__device__ __forceinline__ void bfsplit2(float a, float b, uint32_t& h, uint32_t& l) {
    __nv_bfloat162 hb = __floats2bfloat162_rn(a, b);
    float ra = a - __bfloat162float(hb.x);
    float rb = b - __bfloat162float(hb.y);
    __nv_bfloat162 lb = __floats2bfloat162_rn(ra, rb);
    h = *reinterpret_cast<uint32_t*>(&hb);
    l = *reinterpret_cast<uint32_t*>(&lb);
}

__device__ __forceinline__ void ldsm_x4(uint32_t addr, uint32_t& r0, uint32_t& r1, uint32_t& r2, uint32_t& r3) {
    asm volatile("ldmatrix.sync.aligned.m8n8.x4.shared.b16 {%0,%1,%2,%3}, [%4];"
                 : "=r"(r0), "=r"(r1), "=r"(r2), "=r"(r3) : "r"(addr));
}
__device__ __forceinline__ void ldsm_x4_t(uint32_t addr, uint32_t& r0, uint32_t& r1, uint32_t& r2, uint32_t& r3) {
    asm volatile("ldmatrix.sync.aligned.m8n8.x4.trans.shared.b16 {%0,%1,%2,%3}, [%4];"
                 : "=r"(r0), "=r"(r1), "=r"(r2), "=r"(r3) : "r"(addr));
}
__device__ __forceinline__ void mma16816(float* d, const uint32_t* a, const uint32_t* b) {
    asm volatile("mma.sync.aligned.m16n8k16.row.col.f32.bf16.bf16.f32 "
                 "{%0,%1,%2,%3}, {%4,%5,%6,%7}, {%8,%9}, {%0,%1,%2,%3};"
                 : "+f"(d[0]), "+f"(d[1]), "+f"(d[2]), "+f"(d[3])
                 : "r"(a[0]), "r"(a[1]), "r"(a[2]), "r"(a[3]), "r"(b[0]), "r"(b[1]));
}

#define CP16(dst, src) \
    asm volatile("cp.async.cg.shared.global [%0], [%1], 16;" :: "r"(dst), "l"(src) : "memory")
#define CP_COMMIT() asm volatile("cp.async.commit_group;" ::: "memory")
#define CP_WAIT0()  asm volatile("cp.async.wait_group 0;" ::: "memory")
#define CP_WAIT1()  asm volatile("cp.async.wait_group 1;" ::: "memory")

// ---------------- merged weight pre-split: all 5 matrices, fp32 -> bf16 h/l planes ----------------
__global__ void wsplit_all_k(const float* __restrict__ w_in, const float* __restrict__ w1,
                             const float* __restrict__ w2, const float* __restrict__ w3,
                             const float* __restrict__ w_out, uint16_t* __restrict__ wsp) {
    int i = blockIdx.x * 256 + threadIdx.x;      // global pair index, total 573440
    const float* src;
    size_t pbase;
    int local;
    if (i < 73728)       { src = w_in;  pbase = 0;      local = i; }
    else if (i < 335872) { src = w1;    pbase = 147456; local = i - 73728; }
    else if (i < 466944) { src = w2;    pbase = 671744; local = i - 335872; }
    else if (i < 499712) { src = w3;    pbase = 933888; local = i - 466944; }
    else                 { src = w_out; pbase = 999424; local = i - 499712; }
    float2 v = *(const float2*)(src + (size_t)local * 2);
    uint32_t hh, ll;
    bfsplit2(v.x, v.y, hh, ll);
    *(uint32_t*)(wsp + pbase + (size_t)local * 2) = hh;
    *(uint32_t*)(wsp + 1146880 + pbase + (size_t)local * 2) = ll;
}

// ---------------- warp-MMA bf16-split GEMM (pre-split operands, cp.async) ----------------
#define A_PITCH 80
#define B_PITCH 272
#define AH_OFF 0
#define AL_OFF 10240
#define BH_OFF 20480
#define BL_OFF 29184
#define STG 37888
#define TG_DSMEM (2 * STG + 1024)

__global__ void __launch_bounds__(256, 2) tgemm_k(
    int M, int K,
    const uint16_t* __restrict__ Ah, const uint16_t* __restrict__ Al,
    const uint16_t* __restrict__ Bh, const uint16_t* __restrict__ Bl,
    float* __restrict__ C, uint16_t* __restrict__ Ch, uint16_t* __restrict__ Cl,
    const float* __restrict__ bias, const float* __restrict__ residual, int act)
{
    extern __shared__ char dsm[];
    uint32_t dynu = smem_to_u32(dsm);
    uint32_t base = (dynu + 1023u) & ~1023u;

    int tid = threadIdx.x;
    int lane = tid & 31, warp = tid >> 5;
    int wm = warp & 1, wn = warp >> 1;
    int pix0 = blockIdx.x * 128;
    int rowA = blockIdx.y * 128;

    float acc[4][4][4];
#pragma unroll
    for (int i = 0; i < 4; i++)
#pragma unroll
        for (int j = 0; j < 4; j++)
#pragma unroll
            for (int q = 0; q < 4; q++) acc[i][j][q] = 0.f;

#define ISSUE(t, buf) do { \
    uint32_t s = base + (buf) * STG; \
    int k0 = (t) << 5; \
    _Pragma("unroll") \
    for (int i = 0; i < 2; i++) { \
        int c = tid * 2 + i; \
        int ar = c >> 2, akc = c & 3; \
        size_t aoff = (size_t)(rowA + ar) * K + k0 + akc * 8; \
        uint32_t da = s + AH_OFF + ar * A_PITCH + akc * 16; \
        CP16(da, Ah + aoff); \
        CP16(da + (AL_OFF - AH_OFF), Al + aoff); \
        int br = c >> 4, bnc = c & 15; \
        size_t boff = (size_t)(k0 + br) * HW + pix0 + bnc * 8; \
        uint32_t db = s + BH_OFF + br * B_PITCH + bnc * 16; \
        CP16(db, Bh + boff); \
        CP16(db + (BL_OFF - BH_OFF), Bl + boff); \
    } \
    CP_COMMIT(); \
} while (0)

    int nt = K >> 5;
    ISSUE(0, 0);

    for (int t = 0; t < nt; t++) {
        if (t + 1 < nt) { ISSUE(t + 1, (t + 1) & 1); CP_WAIT1(); }
        else            { CP_WAIT0(); }
        __syncthreads();

        uint32_t sbase = base + (t & 1) * STG;
#pragma unroll
        for (int kk = 0; kk < 2; kk++) {
            uint32_t bh[4][2], bl[4][2];
#pragma unroll
            for (int nj2 = 0; nj2 < 2; nj2++) {
                uint32_t addrh = sbase + BH_OFF + ((lane & 15) + kk * 16) * B_PITCH
                               + wn * 64 + nj2 * 32 + (lane >> 4) * 16;
                ldsm_x4_t(addrh, bh[nj2 * 2][0], bh[nj2 * 2][1], bh[nj2 * 2 + 1][0], bh[nj2 * 2 + 1][1]);
                ldsm_x4_t(addrh + (BL_OFF - BH_OFF),
                          bl[nj2 * 2][0], bl[nj2 * 2][1], bl[nj2 * 2 + 1][0], bl[nj2 * 2 + 1][1]);
            }
#pragma unroll
            for (int mi = 0; mi < 4; mi++) {
                uint32_t ah[4], al[4];
                uint32_t addr = sbase + AH_OFF + (wm * 64 + mi * 16 + (lane & 15)) * A_PITCH
                              + kk * 32 + (lane >> 4) * 16;
                ldsm_x4(addr, ah[0], ah[1], ah[2], ah[3]);
                ldsm_x4(addr + (AL_OFF - AH_OFF), al[0], al[1], al[2], al[3]);
#pragma unroll
                for (int nj = 0; nj < 4; nj++) {
                    mma16816(acc[mi][nj], ah, bh[nj]);
                    mma16816(acc[mi][nj], ah, bl[nj]);
                    mma16816(acc[mi][nj], al, bh[nj]);
                }
            }
        }
        __syncthreads();
    }

#pragma unroll
    for (int mi = 0; mi < 4; mi++) {
        int r0 = rowA + wm * 64 + mi * 16 + (lane >> 2);
        int r1 = r0 + 8;
        float b0 = bias[r0], b1 = bias[r1];
#pragma unroll
        for (int nj = 0; nj < 4; nj++) {
            int col = pix0 + wn * 32 + nj * 8 + (lane & 3) * 2;
            float2 v0, v1;
            v0.x = acc[mi][nj][0] + b0; v0.y = acc[mi][nj][1] + b0;
            v1.x = acc[mi][nj][2] + b1; v1.y = acc[mi][nj][3] + b1;
            if (act) {
                v0.x = gelu_exact(v0.x); v0.y = gelu_exact(v0.y);
                v1.x = gelu_exact(v1.x); v1.y = gelu_exact(v1.y);
            }
            if (C) {
                if (residual) {
                    float2 q0 = *(const float2*)(residual + (size_t)r0 * HW + col);
                    float2 q1 = *(const float2*)(residual + (size_t)r1 * HW + col);
                    v0.x += q0.x; v0.y += q0.y;
                    v1.x += q1.x; v1.y += q1.y;
                }
                *(float2*)(C + (size_t)r0 * HW + col) = v0;
                *(float2*)(C + (size_t)r1 * HW + col) = v1;
            } else {
                uint32_t h, l;
                bfsplit2(v0.x, v0.y, h, l);
                *(uint32_t*)(Ch + (size_t)r0 * HW + col) = h;
                *(uint32_t*)(Cl + (size_t)r0 * HW + col) = l;
                bfsplit2(v1.x, v1.y, h, l);
                *(uint32_t*)(Ch + (size_t)r1 * HW + col) = h;
                *(uint32_t*)(Cl + (size_t)r1 * HW + col) = l;
            }
        }
    }
}

// ---------------- merged feat transpose: all 4 levels, (N,C,HW) -> (N,HW,C) ----------------
__global__ void transpose_all_k(const float* __restrict__ f0, const float* __restrict__ f1,
                                const float* __restrict__ f2, const float* __restrict__ f3,
                                float* __restrict__ out) {
    __shared__ float tile[32][33];
    int bx = blockIdx.x;
    const float* in;
    int hw, ooff, tx0;
    if (bx < 88)       { in = f0; hw = 2816; ooff = 0;     tx0 = bx; }
    else if (bx < 110) { in = f1; hw = 704;  ooff = 16896; tx0 = bx - 88; }
    else if (bx < 116) { in = f2; hw = 176;  ooff = 21120; tx0 = bx - 110; }
    else               { in = f3; hw = 44;   ooff = 22176; tx0 = bx - 116; }
    int n = blockIdx.z;
    int posBase = tx0 * 32;
    int cBase = blockIdx.y * 32;
    int x = posBase + threadIdx.x;
    for (int i = threadIdx.y; i < 32; i += 8) {
        int c = cBase + i;
        if (x < hw) tile[i][threadIdx.x] = in[((size_t)n * 128 + c) * hw + x];
    }
    __syncthreads();
    for (int i = threadIdx.y; i < 32; i += 8) {
        int pos = posBase + i;
        if (pos < hw)
            out[((size_t)(ooff + n * hw + pos)) * 128 + cBase + threadIdx.x] = tile[threadIdx.x][i];
    }
}

// ---------------- im2col -> bf16 h/l planes ----------------
__global__ void im2col_k(const float* __restrict__ in,
                         uint16_t* __restrict__ h, uint16_t* __restrict__ l) {
    int idx = blockIdx.x * 256 + threadIdx.x;    // total 1152*8192
    if (idx >= 1152 * 8192) return;
    int pix2 = (idx & 8191) * 2;
    int kcol = idx >> 13;
    int ci = kcol / 9;
    int t = kcol - ci * 9;
    int dy = t / 3 - 1, dx = t % 3 - 1;
    int y = (pix2 >> 7) + dy;
    int x = (pix2 & 127) + dx;
    float v0 = 0.f, v1 = 0.f;
    if ((unsigned)y < 128u) {
        if ((unsigned)x < 128u)       v0 = in[ci * 16384 + y * 128 + x];
        if ((unsigned)(x + 1) < 128u) v1 = in[ci * 16384 + y * 128 + x + 1];
    }
    uint32_t hh, ll;
    bfsplit2(v0, v1, hh, ll);
    size_t off = (size_t)kcol * 16384 + pix2;
    *(uint32_t*)(h + off) = hh;
    *(uint32_t*)(l + off) = ll;
}

// ---------------- instance norm per channel over 16384 spatial ----------------
__global__ void inorm_k(const float* __restrict__ in, float* __restrict__ out) {
    __shared__ float red[20];
    int c = blockIdx.x, tid = threadIdx.x;
    const float* row = in + (size_t)c * HW;
    float s = 0.f, q = 0.f;
    for (int i = tid; i < HW; i += 256) { float v = row[i]; s += v; q += v * v; }
#pragma unroll
    for (int o = 16; o; o >>= 1) { s += __shfl_down_sync(~0u, s, o); q += __shfl_down_sync(~0u, q, o); }
    if ((tid & 31) == 0) { red[tid >> 5] = s; red[8 + (tid >> 5)] = q; }
    __syncthreads();
    if (tid == 0) {
        float ts = 0.f, tq = 0.f;
        for (int w = 0; w < 8; w++) { ts += red[w]; tq += red[8 + w]; }
        float m = ts * (1.f / HW);
        red[16] = m;
        red[17] = rsqrtf(tq * (1.f / HW) - m * m + 1e-5f);
    }
    __syncthreads();
    float m = red[16], inv = red[17];
    for (int i = tid; i < HW; i += 256)
        out[(size_t)c * HW + i] = (row[i] - m) * inv;
}

// ---------------- offsets / scale-weights / pts / height (64 px per block) ----------------
__global__ void __launch_bounds__(256) stageB_k(
    const float* __restrict__ q1, const float* __restrict__ bev_pos,
    const float* __restrict__ off_w, const float* __restrict__ off_b,
    const float* __restrict__ sw_w, const float* __restrict__ sw_b,
    float* __restrict__ pts, float* __restrict__ swout, float* __restrict__ height)
{
    __shared__ float qs[128][64];
    __shared__ float sres[56][64];
    int tid = threadIdx.x;
    int pix0 = blockIdx.x * 64;

#pragma unroll
    for (int i = 0; i < 32; i++) {
        int idx = tid + i * 256;
        int c = idx >> 6, px = idx & 63;
        qs[c][px] = q1[(size_t)c * HW + pix0 + px];
    }
    __syncthreads();

#pragma unroll
    for (int i = 0; i < 14; i++) {
        int j = tid + i * 256;
        int px = j & 63, o = j >> 6;
        const float* wrow = (o < 24) ? (off_w + o * 128) : (sw_w + (o - 24) * 128);
        float a = (o < 24) ? off_b[o] : sw_b[o - 24];
#pragma unroll 8
        for (int k = 0; k < 128; k++) a = fmaf(wrow[k], qs[k][px], a);
        sres[o][px] = a;
    }
    __syncthreads();

#pragma unroll
    for (int i = 0; i < 2; i++) {
        int j = tid + i * 256;
        int px = j & 63, p = j >> 6;
        int pix = pix0 + px;
        const float LXY = 0.25f + 1e-6f, LZ = 4.0f + 1e-6f;
        float sx = 1.f / (1.f + expf(-sres[p * 3 + 0][px]));
        float sy = 1.f / (1.f + expf(-sres[p * 3 + 1][px]));
        float sz = 1.f / (1.f + expf(-sres[p * 3 + 2][px]));
        float ox = sx * 2.f * LXY - LXY;
        float oy = sy * 2.f * LXY - LXY;
        float oz = sz * 2.f * LZ - LZ;
        float rx = bev_pos[pix * 3 + 0] * 100.f - 50.f;
        float ry = bev_pos[pix * 3 + 1] * 100.f - 50.f;
        float rz = bev_pos[pix * 3 + 2] * 8.f - 4.f;
        pts[pix * 24 + p * 3 + 0] = rx + ox;
        pts[pix * 24 + p * 3 + 1] = ry + oy;
        pts[pix * 24 + p * 3 + 2] = rz + oz;
        height[p * HW + pix] = oz;
        float l0 = sres[24 + p * 4 + 0][px], l1 = sres[24 + p * 4 + 1][px];
        float l2 = sres[24 + p * 4 + 2][px], l3 = sres[24 + p * 4 + 3][px];
        float mx = fmaxf(fmaxf(l0, l1), fmaxf(l2, l3));
        float e0 = expf(l0 - mx), e1 = expf(l1 - mx), e2 = expf(l2 - mx), e3 = expf(l3 - mx);
        float inv = 1.f / (e0 + e1 + e2 + e3);
        swout[pix * 32 + p * 4 + 0] = e0 * inv;
        swout[pix * 32 + p * 4 + 1] = e1 * inv;
        swout[pix * 32 + p * 4 + 2] = e2 * inv;
        swout[pix * 32 + p * 4 + 3] = e3 * inv;
    }
}

// ---------------- fused projection + bilinear sampling + PE MLP ----------------
// grid (1024): each block owns 16 pixels and loops all 8 points -> L1 reuse across points.
__global__ void __launch_bounds__(128) sample_k(
    const float* __restrict__ pts, const float* __restrict__ sww,
    const float* __restrict__ l2i,
    const float* __restrict__ pe_w1, const float* __restrict__ pe_b1,
    const float* __restrict__ pe_w2, const float* __restrict__ pe_b2,
    uint16_t* __restrict__ outh, uint16_t* __restrict__ outl)
{
    const int PIX = 16;
    __shared__ float sM[72];
    __shared__ float sPts[PIX][3];
    __shared__ float sSw[PIX][4];
    __shared__ float sH[256][PIX];
    __shared__ float sOut[PIX][133];

    int pix0 = blockIdx.x * PIX;
    int tid = threadIdx.x;
    int warp = tid >> 5, lane = tid & 31;
    const int HS[4] = {32, 16, 8, 4};
    const int WS[4] = {88, 44, 22, 11};
    const int OFF[4] = {0, 16896, 21120, 22176};

    if (tid < 72) sM[tid] = l2i[(tid / 12) * 16 + (tid % 12)];

    for (int p = 0; p < 8; p++) {
        __syncthreads();   // previous iteration's reads of sPts/sSw/sOut complete
        if (tid < PIX) {
            int pix = pix0 + tid;
            sPts[tid][0] = pts[pix * 24 + p * 3 + 0];
            sPts[tid][1] = pts[pix * 24 + p * 3 + 1];
            sPts[tid][2] = pts[pix * 24 + p * 3 + 2];
        } else if (tid < 2 * PIX) {
            int s = tid - PIX;
            int pix = pix0 + s;
            sSw[s][0] = sww[pix * 32 + p * 4 + 0];
            sSw[s][1] = sww[pix * 32 + p * 4 + 1];
            sSw[s][2] = sww[pix * 32 + p * 4 + 2];
            sSw[s][3] = sww[pix * 32 + p * 4 + 3];
        }
        __syncthreads();

        // PE hidden layer
        for (int j = tid; j < PIX * 256; j += 128) {
            int s = j & (PIX - 1);
            int j2 = j >> 4;
            float xn = (sPts[s][0] + 50.f) * 0.01f;
            float yn = (sPts[s][1] + 50.f) * 0.01f;
            float zn = (sPts[s][2] + 4.f) * 0.125f;
            float h = pe_b1[j2] + xn * pe_w1[j2] + yn * pe_w1[256 + j2] + zn * pe_w1[512 + j2];
            sH[j2][s] = fmaxf(h, 0.f);
        }
        __syncthreads();

        // PE layer-2 GEMV, sharing pe_w2 loads across the warp's 4 pixels
        float4 accp[4];
#pragma unroll
        for (int pp = 0; pp < 4; pp++) accp[pp] = *(const float4*)(pe_b2 + lane * 4);
        for (int j2 = 0; j2 < 256; j2++) {
            float4 w = *(const float4*)(pe_w2 + j2 * 128 + lane * 4);
#pragma unroll
            for (int pp = 0; pp < 4; pp++) {
                float hv = sH[j2][warp * 4 + pp];
                accp[pp].x = fmaf(hv, w.x, accp[pp].x);
                accp[pp].y = fmaf(hv, w.y, accp[pp].y);
                accp[pp].z = fmaf(hv, w.z, accp[pp].z);
                accp[pp].w = fmaf(hv, w.w, accp[pp].w);
            }
        }

        for (int it = 0; it < 4; it++) {
            int pl = warp * 4 + it;
            float X = sPts[pl][0], Y = sPts[pl][1], Z = sPts[pl][2];
            float4 acc = accp[it];
            float swl[4] = {sSw[pl][0], sSw[pl][1], sSw[pl][2], sSw[pl][3]};

            for (int n = 0; n < NCAM; n++) {
                const float* M = sM + n * 12;
                float cx = M[0] * X + M[1] * Y + M[2] * Z + M[3];
                float cy = M[4] * X + M[5] * Y + M[6] * Z + M[7];
                float cz = M[8] * X + M[9] * Y + M[10] * Z + M[11];
                if (cz <= 1e-5f) continue;
                float u = cx / cz * (1.f / 704.f);
                float v = cy / cz * (1.f / 256.f);
#pragma unroll
                for (int l = 0; l < 4; l++) {
                    int Wl = WS[l], Hl = HS[l];
                    float pxf = u * (float)Wl - 0.5f;
                    float pyf = v * (float)Hl - 0.5f;
                    float fx = floorf(pxf), fy = floorf(pyf);
                    int x0 = (int)fx, y0 = (int)fy;
                    if (x0 >= Wl || y0 >= Hl || x0 < -1 || y0 < -1) continue;
                    float wx = pxf - fx, wy = pyf - fy;
                    float g = swl[l];
                    int base = OFF[l] + n * Hl * Wl;
                    bool xl = (x0 >= 0), xr = (x0 + 1 < Wl);
                    bool yt = (y0 >= 0), yb = (y0 + 1 < Hl);
                    if (xl && yt) {
                        float w00 = g * (1.f - wx) * (1.f - wy);
                        float4 t = *(const float4*)(g_ftr + (size_t)(base + y0 * Wl + x0) * 128 + lane * 4);
                        acc.x = fmaf(w00, t.x, acc.x); acc.y = fmaf(w00, t.y, acc.y);
                        acc.z = fmaf(w00, t.z, acc.z); acc.w = fmaf(w00, t.w, acc.w);
                    }
                    if (xr && yt) {
                        float w10 = g * wx * (1.f - wy);
                        float4 t = *(const float4*)(g_ftr + (size_t)(base + y0 * Wl + x0 + 1) * 128 + lane * 4);
                        acc.x = fmaf(w10, t.x, acc.x); acc.y = fmaf(w10, t.y, acc.y);
                        acc.z = fmaf(w10, t.z, acc.z); acc.w = fmaf(w10, t.w, acc.w);
                    }
                    if (xl && yb) {
                        float w01 = g * (1.f - wx) * wy;
                        float4 t = *(const float4*)(g_ftr + (size_t)(base + (y0 + 1) * Wl + x0) * 128 + lane * 4);
                        acc.x = fmaf(w01, t.x, acc.x); acc.y = fmaf(w01, t.y, acc.y);
                        acc.z = fmaf(w01, t.z, acc.z); acc.w = fmaf(w01, t.w, acc.w);
                    }
                    if (xr && yb) {
                        float w11 = g * wx * wy;
                        float4 t = *(const float4*)(g_ftr + (size_t)(base + (y0 + 1) * Wl + x0 + 1) * 128 + lane * 4);
                        acc.x = fmaf(w11, t.x, acc.x); acc.y = fmaf(w11, t.y, acc.y);
                        acc.z = fmaf(w11, t.z, acc.z); acc.w = fmaf(w11, t.w, acc.w);
                    }
                }
            }
            sOut[pl][lane * 4 + 0] = acc.x;
            sOut[pl][lane * 4 + 1] = acc.y;
            sOut[pl][lane * 4 + 2] = acc.z;
            sOut[pl][lane * 4 + 3] = acc.w;
        }
        __syncthreads();
        for (int j = tid; j < PIX * 64; j += 128) {
            int c = j >> 3;
            int px = (j & 7) * 2;
            uint32_t h, l;
            bfsplit2(sOut[px][c], sOut[px + 1][c], h, l);
            size_t addr = ((size_t)(p * 128 + c)) * HW + pix0 + px;
            *(uint32_t*)(outh + addr) = h;
            *(uint32_t*)(outl + addr) = l;
        }
    }
}

// ---------------- host launch ----------------
static void launch_tgemm(int M, int K,
                         const uint16_t* Ah, const uint16_t* Al,
                         const uint16_t* Bh, const uint16_t* Bl,
                         float* C, uint16_t* Ch, uint16_t* Cl,
                         const float* bias, const float* residual, int act) {
    static int attr_set = 0;
    if (!attr_set) {
        cudaFuncSetAttribute(tgemm_k, cudaFuncAttributeMaxDynamicSharedMemorySize, TG_DSMEM);
        attr_set = 1;
    }
    tgemm_k<<<dim3(128, M / 128), 256, TG_DSMEM>>>(M, K, Ah, Al, Bh, Bl, C, Ch, Cl, bias, residual, act);
}

extern "C" void kernel_launch(void* const* d_in, const int* in_sizes, int n_in,
                              void* d_out, int out_size) {
    const float* feat[4] = {(const float*)d_in[0], (const float*)d_in[1],
                            (const float*)d_in[2], (const float*)d_in[3]};
    const float* l2i = (const float*)d_in[4];
    const float* bev_query = (const float*)d_in[5];
    const float* bev_pos = (const float*)d_in[6];
    const float* in_w = (const float*)d_in[7];
    const float* in_b = (const float*)d_in[8];
    const float* off_w = (const float*)d_in[9];
    const float* off_b = (const float*)d_in[10];
    const float* sw_w = (const float*)d_in[11];
    const float* sw_b = (const float*)d_in[12];
    const float* pe_w1 = (const float*)d_in[13];
    const float* pe_b1 = (const float*)d_in[14];
    const float* pe_w2 = (const float*)d_in[15];
    const float* pe_b2 = (const float*)d_in[16];
    const float* mid_w1 = (const float*)d_in[17];
    const float* mid_b1 = (const float*)d_in[18];
    const float* mid_w2 = (const float*)d_in[19];
    const float* mid_b2 = (const float*)d_in[20];
    const float* mid_w3 = (const float*)d_in[21];
    const float* mid_b3 = (const float*)d_in[22];
    const float* out_w = (const float*)d_in[23];
    const float* out_b = (const float*)d_in[24];
    float* out = (float*)d_out;

    float *ftr, *col, *y, *q1, *q2, *ptsb, *swb, *asf, *m1, *m2;
    uint16_t* wsp;
    cudaGetSymbolAddress((void**)&ftr, g_ftr);
    cudaGetSymbolAddress((void**)&col, g_col);
    cudaGetSymbolAddress((void**)&y, g_y);
    cudaGetSymbolAddress((void**)&q1, g_q1);
    cudaGetSymbolAddress((void**)&q2, g_q2);
    cudaGetSymbolAddress((void**)&ptsb, g_pts);
    cudaGetSymbolAddress((void**)&swb, g_swm);
    cudaGetSymbolAddress((void**)&asf, g_asf);
    cudaGetSymbolAddress((void**)&m1, g_m1);
    cudaGetSymbolAddress((void**)&m2, g_m2);
    cudaGetSymbolAddress((void**)&wsp, g_wsp);

    uint16_t* colh = (uint16_t*)col;            uint16_t* coll = colh + (size_t)1152 * 16384;
    uint16_t* asfh = (uint16_t*)asf;            uint16_t* asfl = asfh + (size_t)1024 * 16384;
    uint16_t* m1h  = (uint16_t*)m1;             uint16_t* m1l  = m1h  + (size_t)512 * 16384;
    uint16_t* m2h  = (uint16_t*)m2;             uint16_t* m2l  = m2h  + (size_t)512 * 16384;
    const size_t WTOT = 1146880;
    uint16_t* w_in_h  = wsp;                    uint16_t* w_in_l  = wsp + WTOT;
    uint16_t* w_m1_h  = wsp + 147456;           uint16_t* w_m1_l  = w_m1_h + WTOT;
    uint16_t* w_m2_h  = wsp + 671744;           uint16_t* w_m2_l  = w_m2_h + WTOT;
    uint16_t* w_m3_h  = wsp + 933888;           uint16_t* w_m3_l  = w_m3_h + WTOT;
    uint16_t* w_out_h = wsp + 999424;           uint16_t* w_out_l = w_out_h + WTOT;

    // 0. pre-split all weights (one launch)
    wsplit_all_k<<<2240, 256>>>(in_w, mid_w1, mid_w2, mid_w3, out_w, wsp);

    // 1. transpose feats to channel-last (one launch, all levels)
    transpose_all_k<<<dim3(118, 4, 6), dim3(32, 8)>>>(feat[0], feat[1], feat[2], feat[3], ftr);

    // 2. conv_in + residual -> y ; inorm -> q1
    im2col_k<<<(1152 * 8192) / 256, 256>>>(bev_query, colh, coll);
    launch_tgemm(128, 1152, w_in_h, w_in_l, colh, coll, y, nullptr, nullptr, in_b, bev_query, 0);
    inorm_k<<<128, 256>>>(y, q1);

    // 3. offsets / scale weights / pts / height
    stageB_k<<<256, 256>>>(q1, bev_pos, off_w, off_b, sw_w, sw_b, ptsb, swb, out + 128 * HW);

    // 4. sampling + PE -> asf bf16 planes (p loop inside block for L1 reuse)
    sample_k<<<1024, 128>>>(ptsb, swb, l2i, pe_w1, pe_b1, pe_w2, pe_b2, asfh, asfl);

    // 5. mid MLP chain
    launch_tgemm(512, 1024, w_m1_h, w_m1_l, asfh, asfl, nullptr, m1h, m1l, mid_b1, nullptr, 1);
    launch_tgemm(512,  512, w_m2_h, w_m2_l, m1h,  m1l,  nullptr, m2h, m2l, mid_b2, nullptr, 1);
    launch_tgemm(128,  512, w_m3_h, w_m3_l, m2h,  m2l,  y, nullptr, nullptr, mid_b3, q1, 0);
    inorm_k<<<128, 256>>>(y, q2);

    // 6. conv_out + residual ; final inorm -> d_out (q)
    im2col_k<<<(1152 * 8192) / 256, 256>>>(q2, colh, coll);
    launch_tgemm(128, 1152, w_out_h, w_out_l, colh, coll, y, nullptr, nullptr, out_b, q2, 0);
    inorm_k<<<128, 256>>>(y, out);
}

// round 13
// speedup vs baseline: 1.0484x; 1.0484x over previous
#include <cuda_runtime.h>
#include <cuda_bf16.h>
#include <math.h>
#include <stdint.h>

#define HW 16384   // 128x128 BEV
#define NCAM 6

// ---------------- scratch (static device allocations; no cudaMalloc) ----------------
__device__ float g_ftr[22440 * 128];        // feats transposed channel-last, all levels
__device__ float g_col[1152 * 16384];       // im2col h/l bf16 planes (reused both convs)
__device__ float g_y[128 * 16384];          // pre-norm accumulator (reused)
__device__ float g_q1[128 * 16384];
__device__ float g_q2[128 * 16384];
__device__ float g_pts[16384 * 24];
__device__ float g_swm[16384 * 32];
__device__ float g_asf[1024 * 16384];       // h/l bf16 planes
__device__ float g_m1[512 * 16384];         // h/l bf16 planes
__device__ float g_m2[512 * 16384];         // h/l bf16 planes
__device__ uint16_t g_wsp[2 * 1146880];     // pre-split weights (h plane, then l plane)

// ---------------- helpers ----------------
__device__ __forceinline__ float gelu_exact(float x) { return x * normcdff(x); }

__device__ __forceinline__ uint32_t smem_to_u32(const void* p) {
    uint32_t a;
    asm("{ .reg .u64 t; cvta.to.shared.u64 t, %1; cvt.u32.u64 %0, t; }" : "=r"(a) : "l"(p));
    return a;
}

__device__ __forceinline__ void bfsplit2(float a, float b, uint32_t& h, uint32_t& l) {
    __nv_bfloat162 hb = __floats2bfloat162_rn(a, b);
    float ra = a - __bfloat162float(hb.x);
    float rb = b - __bfloat162float(hb.y);
    __nv_bfloat162 lb = __floats2bfloat162_rn(ra, rb);
    h = *reinterpret_cast<uint32_t*>(&hb);
    l = *reinterpret_cast<uint32_t*>(&lb);
}

__device__ __forceinline__ void ldsm_x4(uint32_t addr, uint32_t& r0, uint32_t& r1, uint32_t& r2, uint32_t& r3) {
    asm volatile("ldmatrix.sync.aligned.m8n8.x4.shared.b16 {%0,%1,%2,%3}, [%4];"
                 : "=r"(r0), "=r"(r1), "=r"(r2), "=r"(r3) : "r"(addr));
}
__device__ __forceinline__ void ldsm_x4_t(uint32_t addr, uint32_t& r0, uint32_t& r1, uint32_t& r2, uint32_t& r3) {
    asm volatile("ldmatrix.sync.aligned.m8n8.x4.trans.shared.b16 {%0,%1,%2,%3}, [%4];"
                 : "=r"(r0), "=r"(r1), "=r"(r2), "=r"(r3) : "r"(addr));
}
__device__ __forceinline__ void mma16816(float* d, const uint32_t* a, const uint32_t* b) {
    asm volatile("mma.sync.aligned.m16n8k16.row.col.f32.bf16.bf16.f32 "
                 "{%0,%1,%2,%3}, {%4,%5,%6,%7}, {%8,%9}, {%0,%1,%2,%3};"
                 : "+f"(d[0]), "+f"(d[1]), "+f"(d[2]), "+f"(d[3])
                 : "r"(a[0]), "r"(a[1]), "r"(a[2]), "r"(a[3]), "r"(b[0]), "r"(b[1]));
}

#define CP16(dst, src) \
    asm volatile("cp.async.cg.shared.global [%0], [%1], 16;" :: "r"(dst), "l"(src) : "memory")
#define CP_COMMIT() asm volatile("cp.async.commit_group;" ::: "memory")
#define CP_WAITG0() asm volatile("cp.async.wait_group 0;" ::: "memory")
#define CP_WAITG1() asm volatile("cp.async.wait_group 1;" ::: "memory")

// ---------------- merged weight pre-split: all 5 matrices, fp32 -> bf16 h/l planes ----------------
__global__ void wsplit_all_k(const float* __restrict__ w_in, const float* __restrict__ w1,
                             const float* __restrict__ w2, const float* __restrict__ w3,
                             const float* __restrict__ w_out, uint16_t* __restrict__ wsp) {
    int i = blockIdx.x * 256 + threadIdx.x;      // global pair index, total 573440
    const float* src;
    size_t pbase;
    int local;
    if (i < 73728)       { src = w_in;  pbase = 0;      local = i; }
    else if (i < 335872) { src = w1;    pbase = 147456; local = i - 73728; }
    else if (i < 466944) { src = w2;    pbase = 671744; local = i - 335872; }
    else if (i < 499712) { src = w3;    pbase = 933888; local = i - 466944; }
    else                 { src = w_out; pbase = 999424; local = i - 499712; }
    float2 v = *(const float2*)(src + (size_t)local * 2);
    uint32_t hh, ll;
    bfsplit2(v.x, v.y, hh, ll);
    *(uint32_t*)(wsp + pbase + (size_t)local * 2) = hh;
    *(uint32_t*)(wsp + 1146880 + pbase + (size_t)local * 2) = ll;
}

// ---------------- warp-MMA bf16-split GEMM (3-stage cp.async pipeline) ----------------
#define A_PITCH 80
#define B_PITCH 272
#define AH_OFF 0
#define AL_OFF 10240
#define BH_OFF 20480
#define BL_OFF 29184
#define STG 37888
#define TG_DSMEM (3 * STG + 1024)

__global__ void __launch_bounds__(256, 2) tgemm_k(
    int M, int K,
    const uint16_t* __restrict__ Ah, const uint16_t* __restrict__ Al,
    const uint16_t* __restrict__ Bh, const uint16_t* __restrict__ Bl,
    float* __restrict__ C, uint16_t* __restrict__ Ch, uint16_t* __restrict__ Cl,
    const float* __restrict__ bias, const float* __restrict__ residual, int act)
{
    extern __shared__ char dsm[];
    uint32_t dynu = smem_to_u32(dsm);
    uint32_t base = (dynu + 1023u) & ~1023u;

    int tid = threadIdx.x;
    int lane = tid & 31, warp = tid >> 5;
    int wm = warp & 1, wn = warp >> 1;
    int pix0 = blockIdx.x * 128;
    int rowA = blockIdx.y * 128;

    float acc[4][4][4];
#pragma unroll
    for (int i = 0; i < 4; i++)
#pragma unroll
        for (int j = 0; j < 4; j++)
#pragma unroll
            for (int q = 0; q < 4; q++) acc[i][j][q] = 0.f;

#define ISSUE(t, buf) do { \
    uint32_t s = base + (buf) * STG; \
    int k0 = (t) << 5; \
    _Pragma("unroll") \
    for (int i = 0; i < 2; i++) { \
        int c = tid * 2 + i; \
        int ar = c >> 2, akc = c & 3; \
        size_t aoff = (size_t)(rowA + ar) * K + k0 + akc * 8; \
        uint32_t da = s + AH_OFF + ar * A_PITCH + akc * 16; \
        CP16(da, Ah + aoff); \
        CP16(da + (AL_OFF - AH_OFF), Al + aoff); \
        int br = c >> 4, bnc = c & 15; \
        size_t boff = (size_t)(k0 + br) * HW + pix0 + bnc * 8; \
        uint32_t db = s + BH_OFF + br * B_PITCH + bnc * 16; \
        CP16(db, Bh + boff); \
        CP16(db + (BL_OFF - BH_OFF), Bl + boff); \
    } \
    CP_COMMIT(); \
} while (0)

    int nt = K >> 5;
    ISSUE(0, 0);
    ISSUE(1, 1);            // nt >= 16 always here

    int cur = 0, ahead = 2;
    for (int t = 0; t < nt; t++) {
        if (t + 1 < nt) { CP_WAITG1(); } else { CP_WAITG0(); }
        __syncthreads();     // group t visible to all; all compute(t-1) done before slot reuse
        if (t + 2 < nt) ISSUE(t + 2, ahead);

        uint32_t sbase = base + cur * STG;
#pragma unroll
        for (int kk = 0; kk < 2; kk++) {
            uint32_t bh[4][2], bl[4][2];
#pragma unroll
            for (int nj2 = 0; nj2 < 2; nj2++) {
                uint32_t addrh = sbase + BH_OFF + ((lane & 15) + kk * 16) * B_PITCH
                               + wn * 64 + nj2 * 32 + (lane >> 4) * 16;
                ldsm_x4_t(addrh, bh[nj2 * 2][0], bh[nj2 * 2][1], bh[nj2 * 2 + 1][0], bh[nj2 * 2 + 1][1]);
                ldsm_x4_t(addrh + (BL_OFF - BH_OFF),
                          bl[nj2 * 2][0], bl[nj2 * 2][1], bl[nj2 * 2 + 1][0], bl[nj2 * 2 + 1][1]);
            }
#pragma unroll
            for (int mi = 0; mi < 4; mi++) {
                uint32_t ah[4], al[4];
                uint32_t addr = sbase + AH_OFF + (wm * 64 + mi * 16 + (lane & 15)) * A_PITCH
                              + kk * 32 + (lane >> 4) * 16;
                ldsm_x4(addr, ah[0], ah[1], ah[2], ah[3]);
                ldsm_x4(addr + (AL_OFF - AH_OFF), al[0], al[1], al[2], al[3]);
#pragma unroll
                for (int nj = 0; nj < 4; nj++) {
                    mma16816(acc[mi][nj], ah, bh[nj]);
                    mma16816(acc[mi][nj], ah, bl[nj]);
                    mma16816(acc[mi][nj], al, bh[nj]);
                }
            }
        }
        cur = (cur == 2) ? 0 : cur + 1;
        ahead = (ahead == 2) ? 0 : ahead + 1;
    }

#pragma unroll
    for (int mi = 0; mi < 4; mi++) {
        int r0 = rowA + wm * 64 + mi * 16 + (lane >> 2);
        int r1 = r0 + 8;
        float b0 = bias[r0], b1 = bias[r1];
#pragma unroll
        for (int nj = 0; nj < 4; nj++) {
            int col = pix0 + wn * 32 + nj * 8 + (lane & 3) * 2;
            float2 v0, v1;
            v0.x = acc[mi][nj][0] + b0; v0.y = acc[mi][nj][1] + b0;
            v1.x = acc[mi][nj][2] + b1; v1.y = acc[mi][nj][3] + b1;
            if (act) {
                v0.x = gelu_exact(v0.x); v0.y = gelu_exact(v0.y);
                v1.x = gelu_exact(v1.x); v1.y = gelu_exact(v1.y);
            }
            if (C) {
                if (residual) {
                    float2 q0 = *(const float2*)(residual + (size_t)r0 * HW + col);
                    float2 q1 = *(const float2*)(residual + (size_t)r1 * HW + col);
                    v0.x += q0.x; v0.y += q0.y;
                    v1.x += q1.x; v1.y += q1.y;
                }
                *(float2*)(C + (size_t)r0 * HW + col) = v0;
                *(float2*)(C + (size_t)r1 * HW + col) = v1;
            } else {
                uint32_t h, l;
                bfsplit2(v0.x, v0.y, h, l);
                *(uint32_t*)(Ch + (size_t)r0 * HW + col) = h;
                *(uint32_t*)(Cl + (size_t)r0 * HW + col) = l;
                bfsplit2(v1.x, v1.y, h, l);
                *(uint32_t*)(Ch + (size_t)r1 * HW + col) = h;
                *(uint32_t*)(Cl + (size_t)r1 * HW + col) = l;
            }
        }
    }
}

// ---------------- merged feat transpose: all 4 levels, (N,C,HW) -> (N,HW,C) ----------------
__global__ void transpose_all_k(const float* __restrict__ f0, const float* __restrict__ f1,
                                const float* __restrict__ f2, const float* __restrict__ f3,
                                float* __restrict__ out) {
    __shared__ float tile[32][33];
    int bx = blockIdx.x;
    const float* in;
    int hw, ooff, tx0;
    if (bx < 88)       { in = f0; hw = 2816; ooff = 0;     tx0 = bx; }
    else if (bx < 110) { in = f1; hw = 704;  ooff = 16896; tx0 = bx - 88; }
    else if (bx < 116) { in = f2; hw = 176;  ooff = 21120; tx0 = bx - 110; }
    else               { in = f3; hw = 44;   ooff = 22176; tx0 = bx - 116; }
    int n = blockIdx.z;
    int posBase = tx0 * 32;
    int cBase = blockIdx.y * 32;
    int x = posBase + threadIdx.x;
    for (int i = threadIdx.y; i < 32; i += 8) {
        int c = cBase + i;
        if (x < hw) tile[i][threadIdx.x] = in[((size_t)n * 128 + c) * hw + x];
    }
    __syncthreads();
    for (int i = threadIdx.y; i < 32; i += 8) {
        int pos = posBase + i;
        if (pos < hw)
            out[((size_t)(ooff + n * hw + pos)) * 128 + cBase + threadIdx.x] = tile[threadIdx.x][i];
    }
}

// ---------------- im2col -> bf16 h/l planes ----------------
__global__ void im2col_k(const float* __restrict__ in,
                         uint16_t* __restrict__ h, uint16_t* __restrict__ l) {
    int idx = blockIdx.x * 256 + threadIdx.x;    // total 1152*8192
    if (idx >= 1152 * 8192) return;
    int pix2 = (idx & 8191) * 2;
    int kcol = idx >> 13;
    int ci = kcol / 9;
    int t = kcol - ci * 9;
    int dy = t / 3 - 1, dx = t % 3 - 1;
    int y = (pix2 >> 7) + dy;
    int x = (pix2 & 127) + dx;
    float v0 = 0.f, v1 = 0.f;
    if ((unsigned)y < 128u) {
        if ((unsigned)x < 128u)       v0 = in[ci * 16384 + y * 128 + x];
        if ((unsigned)(x + 1) < 128u) v1 = in[ci * 16384 + y * 128 + x + 1];
    }
    uint32_t hh, ll;
    bfsplit2(v0, v1, hh, ll);
    size_t off = (size_t)kcol * 16384 + pix2;
    *(uint32_t*)(h + off) = hh;
    *(uint32_t*)(l + off) = ll;
}

// ---------------- instance norm per channel over 16384 spatial ----------------
__global__ void inorm_k(const float* __restrict__ in, float* __restrict__ out) {
    __shared__ float red[20];
    int c = blockIdx.x, tid = threadIdx.x;
    const float* row = in + (size_t)c * HW;
    float s = 0.f, q = 0.f;
    for (int i = tid; i < HW; i += 256) { float v = row[i]; s += v; q += v * v; }
#pragma unroll
    for (int o = 16; o; o >>= 1) { s += __shfl_down_sync(~0u, s, o); q += __shfl_down_sync(~0u, q, o); }
    if ((tid & 31) == 0) { red[tid >> 5] = s; red[8 + (tid >> 5)] = q; }
    __syncthreads();
    if (tid == 0) {
        float ts = 0.f, tq = 0.f;
        for (int w = 0; w < 8; w++) { ts += red[w]; tq += red[8 + w]; }
        float m = ts * (1.f / HW);
        red[16] = m;
        red[17] = rsqrtf(tq * (1.f / HW) - m * m + 1e-5f);
    }
    __syncthreads();
    float m = red[16], inv = red[17];
    for (int i = tid; i < HW; i += 256)
        out[(size_t)c * HW + i] = (row[i] - m) * inv;
}

// ---------------- offsets / scale-weights / pts / height (64 px per block) ----------------
__global__ void __launch_bounds__(256) stageB_k(
    const float* __restrict__ q1, const float* __restrict__ bev_pos,
    const float* __restrict__ off_w, const float* __restrict__ off_b,
    const float* __restrict__ sw_w, const float* __restrict__ sw_b,
    float* __restrict__ pts, float* __restrict__ swout, float* __restrict__ height)
{
    __shared__ float qs[128][64];
    __shared__ float sres[56][64];
    int tid = threadIdx.x;
    int pix0 = blockIdx.x * 64;

#pragma unroll
    for (int i = 0; i < 32; i++) {
        int idx = tid + i * 256;
        int c = idx >> 6, px = idx & 63;
        qs[c][px] = q1[(size_t)c * HW + pix0 + px];
    }
    __syncthreads();

#pragma unroll
    for (int i = 0; i < 14; i++) {
        int j = tid + i * 256;
        int px = j & 63, o = j >> 6;
        const float* wrow = (o < 24) ? (off_w + o * 128) : (sw_w + (o - 24) * 128);
        float a = (o < 24) ? off_b[o] : sw_b[o - 24];
#pragma unroll 8
        for (int k = 0; k < 128; k++) a = fmaf(wrow[k], qs[k][px], a);
        sres[o][px] = a;
    }
    __syncthreads();

#pragma unroll
    for (int i = 0; i < 2; i++) {
        int j = tid + i * 256;
        int px = j & 63, p = j >> 6;
        int pix = pix0 + px;
        const float LXY = 0.25f + 1e-6f, LZ = 4.0f + 1e-6f;
        float sx = 1.f / (1.f + expf(-sres[p * 3 + 0][px]));
        float sy = 1.f / (1.f + expf(-sres[p * 3 + 1][px]));
        float sz = 1.f / (1.f + expf(-sres[p * 3 + 2][px]));
        float ox = sx * 2.f * LXY - LXY;
        float oy = sy * 2.f * LXY - LXY;
        float oz = sz * 2.f * LZ - LZ;
        float rx = bev_pos[pix * 3 + 0] * 100.f - 50.f;
        float ry = bev_pos[pix * 3 + 1] * 100.f - 50.f;
        float rz = bev_pos[pix * 3 + 2] * 8.f - 4.f;
        pts[pix * 24 + p * 3 + 0] = rx + ox;
        pts[pix * 24 + p * 3 + 1] = ry + oy;
        pts[pix * 24 + p * 3 + 2] = rz + oz;
        height[p * HW + pix] = oz;
        float l0 = sres[24 + p * 4 + 0][px], l1 = sres[24 + p * 4 + 1][px];
        float l2 = sres[24 + p * 4 + 2][px], l3 = sres[24 + p * 4 + 3][px];
        float mx = fmaxf(fmaxf(l0, l1), fmaxf(l2, l3));
        float e0 = expf(l0 - mx), e1 = expf(l1 - mx), e2 = expf(l2 - mx), e3 = expf(l3 - mx);
        float inv = 1.f / (e0 + e1 + e2 + e3);
        swout[pix * 32 + p * 4 + 0] = e0 * inv;
        swout[pix * 32 + p * 4 + 1] = e1 * inv;
        swout[pix * 32 + p * 4 + 2] = e2 * inv;
        swout[pix * 32 + p * 4 + 3] = e3 * inv;
    }
}

// ---------------- fused projection + bilinear sampling + PE MLP (PIX=16 champion) ----------------
__global__ void __launch_bounds__(128) sample_k(
    const float* __restrict__ pts, const float* __restrict__ sww,
    const float* __restrict__ l2i,
    const float* __restrict__ pe_w1, const float* __restrict__ pe_b1,
    const float* __restrict__ pe_w2, const float* __restrict__ pe_b2,
    uint16_t* __restrict__ outh, uint16_t* __restrict__ outl)
{
    const int PIX = 16;
    __shared__ float sM[72];
    __shared__ float sPts[PIX][3];
    __shared__ float sSw[PIX][4];
    __shared__ float sH[256][PIX];
    __shared__ float sOut[PIX][133];

    int p = blockIdx.y;
    int pix0 = blockIdx.x * PIX;
    int tid = threadIdx.x;

    if (tid < 72) sM[tid] = l2i[(tid / 12) * 16 + (tid % 12)];
    if (tid < PIX) {
        int pix = pix0 + tid;
        sPts[tid][0] = pts[pix * 24 + p * 3 + 0];
        sPts[tid][1] = pts[pix * 24 + p * 3 + 1];
        sPts[tid][2] = pts[pix * 24 + p * 3 + 2];
    } else if (tid < 2 * PIX) {
        int s = tid - PIX;
        int pix = pix0 + s;
        sSw[s][0] = sww[pix * 32 + p * 4 + 0];
        sSw[s][1] = sww[pix * 32 + p * 4 + 1];
        sSw[s][2] = sww[pix * 32 + p * 4 + 2];
        sSw[s][3] = sww[pix * 32 + p * 4 + 3];
    }
    __syncthreads();

    for (int j = tid; j < PIX * 256; j += 128) {
        int s = j & (PIX - 1);
        int j2 = j >> 4;
        float xn = (sPts[s][0] + 50.f) * 0.01f;
        float yn = (sPts[s][1] + 50.f) * 0.01f;
        float zn = (sPts[s][2] + 4.f) * 0.125f;
        float h = pe_b1[j2] + xn * pe_w1[j2] + yn * pe_w1[256 + j2] + zn * pe_w1[512 + j2];
        sH[j2][s] = fmaxf(h, 0.f);
    }
    __syncthreads();

    int warp = tid >> 5, lane = tid & 31;
    const int HS[4] = {32, 16, 8, 4};
    const int WS[4] = {88, 44, 22, 11};
    const int OFF[4] = {0, 16896, 21120, 22176};

    float4 accp[4];
#pragma unroll
    for (int pp = 0; pp < 4; pp++) accp[pp] = *(const float4*)(pe_b2 + lane * 4);
    for (int j2 = 0; j2 < 256; j2++) {
        float4 w = *(const float4*)(pe_w2 + j2 * 128 + lane * 4);
#pragma unroll
        for (int pp = 0; pp < 4; pp++) {
            float hv = sH[j2][warp * 4 + pp];
            accp[pp].x = fmaf(hv, w.x, accp[pp].x);
            accp[pp].y = fmaf(hv, w.y, accp[pp].y);
            accp[pp].z = fmaf(hv, w.z, accp[pp].z);
            accp[pp].w = fmaf(hv, w.w, accp[pp].w);
        }
    }

    for (int it = 0; it < 4; it++) {
        int pl = warp * 4 + it;
        float X = sPts[pl][0], Y = sPts[pl][1], Z = sPts[pl][2];
        float4 acc = accp[it];
        float swl[4] = {sSw[pl][0], sSw[pl][1], sSw[pl][2], sSw[pl][3]};

        for (int n = 0; n < NCAM; n++) {
            const float* M = sM + n * 12;
            float cx = M[0] * X + M[1] * Y + M[2] * Z + M[3];
            float cy = M[4] * X + M[5] * Y + M[6] * Z + M[7];
            float cz = M[8] * X + M[9] * Y + M[10] * Z + M[11];
            if (cz <= 1e-5f) continue;
            float u = cx / cz * (1.f / 704.f);
            float v = cy / cz * (1.f / 256.f);
#pragma unroll
            for (int l = 0; l < 4; l++) {
                int Wl = WS[l], Hl = HS[l];
                float pxf = u * (float)Wl - 0.5f;
                float pyf = v * (float)Hl - 0.5f;
                float fx = floorf(pxf), fy = floorf(pyf);
                int x0 = (int)fx, y0 = (int)fy;
                if (x0 >= Wl || y0 >= Hl || x0 < -1 || y0 < -1) continue;
                float wx = pxf - fx, wy = pyf - fy;
                float g = swl[l];
                int base = OFF[l] + n * Hl * Wl;
                bool xl = (x0 >= 0), xr = (x0 + 1 < Wl);
                bool yt = (y0 >= 0), yb = (y0 + 1 < Hl);
                if (xl && yt) {
                    float w00 = g * (1.f - wx) * (1.f - wy);
                    float4 t = *(const float4*)(g_ftr + (size_t)(base + y0 * Wl + x0) * 128 + lane * 4);
                    acc.x = fmaf(w00, t.x, acc.x); acc.y = fmaf(w00, t.y, acc.y);
                    acc.z = fmaf(w00, t.z, acc.z); acc.w = fmaf(w00, t.w, acc.w);
                }
                if (xr && yt) {
                    float w10 = g * wx * (1.f - wy);
                    float4 t = *(const float4*)(g_ftr + (size_t)(base + y0 * Wl + x0 + 1) * 128 + lane * 4);
                    acc.x = fmaf(w10, t.x, acc.x); acc.y = fmaf(w10, t.y, acc.y);
                    acc.z = fmaf(w10, t.z, acc.z); acc.w = fmaf(w10, t.w, acc.w);
                }
                if (xl && yb) {
                    float w01 = g * (1.f - wx) * wy;
                    float4 t = *(const float4*)(g_ftr + (size_t)(base + (y0 + 1) * Wl + x0) * 128 + lane * 4);
                    acc.x = fmaf(w01, t.x, acc.x); acc.y = fmaf(w01, t.y, acc.y);
                    acc.z = fmaf(w01, t.z, acc.z); acc.w = fmaf(w01, t.w, acc.w);
                }
                if (xr && yb) {
                    float w11 = g * wx * wy;
                    float4 t = *(const float4*)(g_ftr + (size_t)(base + (y0 + 1) * Wl + x0 + 1) * 128 + lane * 4);
                    acc.x = fmaf(w11, t.x, acc.x); acc.y = fmaf(w11, t.y, acc.y);
                    acc.z = fmaf(w11, t.z, acc.z); acc.w = fmaf(w11, t.w, acc.w);
                }
            }
        }
        sOut[pl][lane * 4 + 0] = acc.x;
        sOut[pl][lane * 4 + 1] = acc.y;
        sOut[pl][lane * 4 + 2] = acc.z;
        sOut[pl][lane * 4 + 3] = acc.w;
    }
    __syncthreads();
    for (int j = tid; j < PIX * 64; j += 128) {
        int c = j >> 3;
        int px = (j & 7) * 2;
        uint32_t h, l;
        bfsplit2(sOut[px][c], sOut[px + 1][c], h, l);
        size_t addr = ((size_t)(p * 128 + c)) * HW + pix0 + px;
        *(uint32_t*)(outh + addr) = h;
        *(uint32_t*)(outl + addr) = l;
    }
}

// ---------------- host launch ----------------
static void launch_tgemm(int M, int K,
                         const uint16_t* Ah, const uint16_t* Al,
                         const uint16_t* Bh, const uint16_t* Bl,
                         float* C, uint16_t* Ch, uint16_t* Cl,
                         const float* bias, const float* residual, int act) {
    static int attr_set = 0;
    if (!attr_set) {
        cudaFuncSetAttribute(tgemm_k, cudaFuncAttributeMaxDynamicSharedMemorySize, TG_DSMEM);
        attr_set = 1;
    }
    tgemm_k<<<dim3(128, M / 128), 256, TG_DSMEM>>>(M, K, Ah, Al, Bh, Bl, C, Ch, Cl, bias, residual, act);
}

extern "C" void kernel_launch(void* const* d_in, const int* in_sizes, int n_in,
                              void* d_out, int out_size) {
    const float* feat[4] = {(const float*)d_in[0], (const float*)d_in[1],
                            (const float*)d_in[2], (const float*)d_in[3]};
    const float* l2i = (const float*)d_in[4];
    const float* bev_query = (const float*)d_in[5];
    const float* bev_pos = (const float*)d_in[6];
    const float* in_w = (const float*)d_in[7];
    const float* in_b = (const float*)d_in[8];
    const float* off_w = (const float*)d_in[9];
    const float* off_b = (const float*)d_in[10];
    const float* sw_w = (const float*)d_in[11];
    const float* sw_b = (const float*)d_in[12];
    const float* pe_w1 = (const float*)d_in[13];
    const float* pe_b1 = (const float*)d_in[14];
    const float* pe_w2 = (const float*)d_in[15];
    const float* pe_b2 = (const float*)d_in[16];
    const float* mid_w1 = (const float*)d_in[17];
    const float* mid_b1 = (const float*)d_in[18];
    const float* mid_w2 = (const float*)d_in[19];
    const float* mid_b2 = (const float*)d_in[20];
    const float* mid_w3 = (const float*)d_in[21];
    const float* mid_b3 = (const float*)d_in[22];
    const float* out_w = (const float*)d_in[23];
    const float* out_b = (const float*)d_in[24];
    float* out = (float*)d_out;

    float *ftr, *col, *y, *q1, *q2, *ptsb, *swb, *asf, *m1, *m2;
    uint16_t* wsp;
    cudaGetSymbolAddress((void**)&ftr, g_ftr);
    cudaGetSymbolAddress((void**)&col, g_col);
    cudaGetSymbolAddress((void**)&y, g_y);
    cudaGetSymbolAddress((void**)&q1, g_q1);
    cudaGetSymbolAddress((void**)&q2, g_q2);
    cudaGetSymbolAddress((void**)&ptsb, g_pts);
    cudaGetSymbolAddress((void**)&swb, g_swm);
    cudaGetSymbolAddress((void**)&asf, g_asf);
    cudaGetSymbolAddress((void**)&m1, g_m1);
    cudaGetSymbolAddress((void**)&m2, g_m2);
    cudaGetSymbolAddress((void**)&wsp, g_wsp);

    uint16_t* colh = (uint16_t*)col;            uint16_t* coll = colh + (size_t)1152 * 16384;
    uint16_t* asfh = (uint16_t*)asf;            uint16_t* asfl = asfh + (size_t)1024 * 16384;
    uint16_t* m1h  = (uint16_t*)m1;             uint16_t* m1l  = m1h  + (size_t)512 * 16384;
    uint16_t* m2h  = (uint16_t*)m2;             uint16_t* m2l  = m2h  + (size_t)512 * 16384;
    const size_t WTOT = 1146880;
    uint16_t* w_in_h  = wsp;                    uint16_t* w_in_l  = wsp + WTOT;
    uint16_t* w_m1_h  = wsp + 147456;           uint16_t* w_m1_l  = w_m1_h + WTOT;
    uint16_t* w_m2_h  = wsp + 671744;           uint16_t* w_m2_l  = w_m2_h + WTOT;
    uint16_t* w_m3_h  = wsp + 933888;           uint16_t* w_m3_l  = w_m3_h + WTOT;
    uint16_t* w_out_h = wsp + 999424;           uint16_t* w_out_l = w_out_h + WTOT;

    // 0. pre-split all weights (one launch)
    wsplit_all_k<<<2240, 256>>>(in_w, mid_w1, mid_w2, mid_w3, out_w, wsp);

    // 1. transpose feats to channel-last (one launch, all levels)
    transpose_all_k<<<dim3(118, 4, 6), dim3(32, 8)>>>(feat[0], feat[1], feat[2], feat[3], ftr);

    // 2. conv_in + residual -> y ; inorm -> q1
    im2col_k<<<(1152 * 8192) / 256, 256>>>(bev_query, colh, coll);
    launch_tgemm(128, 1152, w_in_h, w_in_l, colh, coll, y, nullptr, nullptr, in_b, bev_query, 0);
    inorm_k<<<128, 256>>>(y, q1);

    // 3. offsets / scale weights / pts / height
    stageB_k<<<256, 256>>>(q1, bev_pos, off_w, off_b, sw_w, sw_b, ptsb, swb, out + 128 * HW);

    // 4. sampling + PE -> asf bf16 planes
    sample_k<<<dim3(1024, 8), 128>>>(ptsb, swb, l2i, pe_w1, pe_b1, pe_w2, pe_b2, asfh, asfl);

    // 5. mid MLP chain
    launch_tgemm(512, 1024, w_m1_h, w_m1_l, asfh, asfl, nullptr, m1h, m1l, mid_b1, nullptr, 1);
    launch_tgemm(512,  512, w_m2_h, w_m2_l, m1h,  m1l,  nullptr, m2h, m2l, mid_b2, nullptr, 1);
    launch_tgemm(128,  512, w_m3_h, w_m3_l, m2h,  m2l,  y, nullptr, nullptr, mid_b3, q1, 0);
    inorm_k<<<128, 256>>>(y, q2);

    // 6. conv_out + residual ; final inorm -> d_out (q)
    im2col_k<<<(1152 * 8192) / 256, 256>>>(q2, colh, coll);
    launch_tgemm(128, 1152, w_out_h, w_out_l, colh, coll, y, nullptr, nullptr, out_b, q2, 0);
    inorm_k<<<128, 256>>>(y, out);
}

// round 14
// speedup vs baseline: 1.0508x; 1.0023x over previous
#include <cuda_runtime.h>
#include <cuda_bf16.h>
#include <cuda_fp16.h>
#include <math.h>
#include <stdint.h>

#define HW 16384   // 128x128 BEV
#define NCAM 6

// ---------------- scratch (static device allocations; no cudaMalloc) ----------------
__device__ __half g_ftr[22440 * 128];       // feats transposed channel-last, fp16
__device__ float g_col[1152 * 16384];       // im2col h/l bf16 planes (reused both convs)
__device__ float g_y[128 * 16384];          // pre-norm accumulator (reused)
__device__ float g_q1[128 * 16384];
__device__ float g_q2[128 * 16384];
__device__ float g_pts[16384 * 24];
__device__ float g_swm[16384 * 32];
__device__ float g_asf[1024 * 16384];       // h/l bf16 planes
__device__ float g_m1[512 * 16384];         // h/l bf16 planes
__device__ float g_m2[512 * 16384];         // h/l bf16 planes
__device__ uint16_t g_wsp[2 * 1146880];     // pre-split weights (h plane, then l plane)

// ---------------- helpers ----------------
__device__ __forceinline__ float gelu_exact(float x) { return x * normcdff(x); }

__device__ __forceinline__ uint32_t smem_to_u32(const void* p) {
    uint32_t a;
    asm("{ .reg .u64 t; cvta.to.shared.u64 t, %1; cvt.u32.u64 %0, t; }" : "=r"(a) : "l"(p));
    return a;
}

__device__ __forceinline__ void bfsplit2(float a, float b, uint32_t& h, uint32_t& l) {
    __nv_bfloat162 hb = __floats2bfloat162_rn(a, b);
    float ra = a - __bfloat162float(hb.x);
    float rb = b - __bfloat162float(hb.y);
    __nv_bfloat162 lb = __floats2bfloat162_rn(ra, rb);
    h = *reinterpret_cast<uint32_t*>(&hb);
    l = *reinterpret_cast<uint32_t*>(&lb);
}

__device__ __forceinline__ void ldsm_x4(uint32_t addr, uint32_t& r0, uint32_t& r1, uint32_t& r2, uint32_t& r3) {
    asm volatile("ldmatrix.sync.aligned.m8n8.x4.shared.b16 {%0,%1,%2,%3}, [%4];"
                 : "=r"(r0), "=r"(r1), "=r"(r2), "=r"(r3) : "r"(addr));
}
__device__ __forceinline__ void ldsm_x4_t(uint32_t addr, uint32_t& r0, uint32_t& r1, uint32_t& r2, uint32_t& r3) {
    asm volatile("ldmatrix.sync.aligned.m8n8.x4.trans.shared.b16 {%0,%1,%2,%3}, [%4];"
                 : "=r"(r0), "=r"(r1), "=r"(r2), "=r"(r3) : "r"(addr));
}
__device__ __forceinline__ void mma16816(float* d, const uint32_t* a, const uint32_t* b) {
    asm volatile("mma.sync.aligned.m16n8k16.row.col.f32.bf16.bf16.f32 "
                 "{%0,%1,%2,%3}, {%4,%5,%6,%7}, {%8,%9}, {%0,%1,%2,%3};"
                 : "+f"(d[0]), "+f"(d[1]), "+f"(d[2]), "+f"(d[3])
                 : "r"(a[0]), "r"(a[1]), "r"(a[2]), "r"(a[3]), "r"(b[0]), "r"(b[1]));
}

#define CP16(dst, src) \
    asm volatile("cp.async.cg.shared.global [%0], [%1], 16;" :: "r"(dst), "l"(src) : "memory")
#define CP_COMMIT() asm volatile("cp.async.commit_group;" ::: "memory")
#define CP_WAITG0() asm volatile("cp.async.wait_group 0;" ::: "memory")
#define CP_WAITG1() asm volatile("cp.async.wait_group 1;" ::: "memory")

// ---------------- merged weight pre-split: all 5 matrices, fp32 -> bf16 h/l planes ----------------
__global__ void wsplit_all_k(const float* __restrict__ w_in, const float* __restrict__ w1,
                             const float* __restrict__ w2, const float* __restrict__ w3,
                             const float* __restrict__ w_out, uint16_t* __restrict__ wsp) {
    int i = blockIdx.x * 256 + threadIdx.x;      // global pair index, total 573440
    const float* src;
    size_t pbase;
    int local;
    if (i < 73728)       { src = w_in;  pbase = 0;      local = i; }
    else if (i < 335872) { src = w1;    pbase = 147456; local = i - 73728; }
    else if (i < 466944) { src = w2;    pbase = 671744; local = i - 335872; }
    else if (i < 499712) { src = w3;    pbase = 933888; local = i - 466944; }
    else                 { src = w_out; pbase = 999424; local = i - 499712; }
    float2 v = *(const float2*)(src + (size_t)local * 2);
    uint32_t hh, ll;
    bfsplit2(v.x, v.y, hh, ll);
    *(uint32_t*)(wsp + pbase + (size_t)local * 2) = hh;
    *(uint32_t*)(wsp + 1146880 + pbase + (size_t)local * 2) = ll;
}

// ---------------- warp-MMA bf16-split GEMM (3-stage cp.async pipeline) ----------------
#define A_PITCH 80
#define B_PITCH 272
#define AH_OFF 0
#define AL_OFF 10240
#define BH_OFF 20480
#define BL_OFF 29184
#define STG 37888
#define TG_DSMEM (3 * STG + 1024)

__global__ void __launch_bounds__(256, 2) tgemm_k(
    int M, int K,
    const uint16_t* __restrict__ Ah, const uint16_t* __restrict__ Al,
    const uint16_t* __restrict__ Bh, const uint16_t* __restrict__ Bl,
    float* __restrict__ C, uint16_t* __restrict__ Ch, uint16_t* __restrict__ Cl,
    const float* __restrict__ bias, const float* __restrict__ residual, int act)
{
    extern __shared__ char dsm[];
    uint32_t dynu = smem_to_u32(dsm);
    uint32_t base = (dynu + 1023u) & ~1023u;

    int tid = threadIdx.x;
    int lane = tid & 31, warp = tid >> 5;
    int wm = warp & 1, wn = warp >> 1;
    int pix0 = blockIdx.x * 128;
    int rowA = blockIdx.y * 128;

    float acc[4][4][4];
#pragma unroll
    for (int i = 0; i < 4; i++)
#pragma unroll
        for (int j = 0; j < 4; j++)
#pragma unroll
            for (int q = 0; q < 4; q++) acc[i][j][q] = 0.f;

#define ISSUE(t, buf) do { \
    uint32_t s = base + (buf) * STG; \
    int k0 = (t) << 5; \
    _Pragma("unroll") \
    for (int i = 0; i < 2; i++) { \
        int c = tid * 2 + i; \
        int ar = c >> 2, akc = c & 3; \
        size_t aoff = (size_t)(rowA + ar) * K + k0 + akc * 8; \
        uint32_t da = s + AH_OFF + ar * A_PITCH + akc * 16; \
        CP16(da, Ah + aoff); \
        CP16(da + (AL_OFF - AH_OFF), Al + aoff); \
        int br = c >> 4, bnc = c & 15; \
        size_t boff = (size_t)(k0 + br) * HW + pix0 + bnc * 8; \
        uint32_t db = s + BH_OFF + br * B_PITCH + bnc * 16; \
        CP16(db, Bh + boff); \
        CP16(db + (BL_OFF - BH_OFF), Bl + boff); \
    } \
    CP_COMMIT(); \
} while (0)

    int nt = K >> 5;
    ISSUE(0, 0);
    ISSUE(1, 1);            // nt >= 16 always here

    int cur = 0, ahead = 2;
    for (int t = 0; t < nt; t++) {
        if (t + 1 < nt) { CP_WAITG1(); } else { CP_WAITG0(); }
        __syncthreads();     // group t visible to all; all compute(t-1) done before slot reuse
        if (t + 2 < nt) ISSUE(t + 2, ahead);

        uint32_t sbase = base + cur * STG;
#pragma unroll
        for (int kk = 0; kk < 2; kk++) {
            uint32_t bh[4][2], bl[4][2];
#pragma unroll
            for (int nj2 = 0; nj2 < 2; nj2++) {
                uint32_t addrh = sbase + BH_OFF + ((lane & 15) + kk * 16) * B_PITCH
                               + wn * 64 + nj2 * 32 + (lane >> 4) * 16;
                ldsm_x4_t(addrh, bh[nj2 * 2][0], bh[nj2 * 2][1], bh[nj2 * 2 + 1][0], bh[nj2 * 2 + 1][1]);
                ldsm_x4_t(addrh + (BL_OFF - BH_OFF),
                          bl[nj2 * 2][0], bl[nj2 * 2][1], bl[nj2 * 2 + 1][0], bl[nj2 * 2 + 1][1]);
            }
#pragma unroll
            for (int mi = 0; mi < 4; mi++) {
                uint32_t ah[4], al[4];
                uint32_t addr = sbase + AH_OFF + (wm * 64 + mi * 16 + (lane & 15)) * A_PITCH
                              + kk * 32 + (lane >> 4) * 16;
                ldsm_x4(addr, ah[0], ah[1], ah[2], ah[3]);
                ldsm_x4(addr + (AL_OFF - AH_OFF), al[0], al[1], al[2], al[3]);
#pragma unroll
                for (int nj = 0; nj < 4; nj++) {
                    mma16816(acc[mi][nj], ah, bh[nj]);
                    mma16816(acc[mi][nj], ah, bl[nj]);
                    mma16816(acc[mi][nj], al, bh[nj]);
                }
            }
        }
        cur = (cur == 2) ? 0 : cur + 1;
        ahead = (ahead == 2) ? 0 : ahead + 1;
    }

#pragma unroll
    for (int mi = 0; mi < 4; mi++) {
        int r0 = rowA + wm * 64 + mi * 16 + (lane >> 2);
        int r1 = r0 + 8;
        float b0 = bias[r0], b1 = bias[r1];
#pragma unroll
        for (int nj = 0; nj < 4; nj++) {
            int col = pix0 + wn * 32 + nj * 8 + (lane & 3) * 2;
            float2 v0, v1;
            v0.x = acc[mi][nj][0] + b0; v0.y = acc[mi][nj][1] + b0;
            v1.x = acc[mi][nj][2] + b1; v1.y = acc[mi][nj][3] + b1;
            if (act) {
                v0.x = gelu_exact(v0.x); v0.y = gelu_exact(v0.y);
                v1.x = gelu_exact(v1.x); v1.y = gelu_exact(v1.y);
            }
            if (C) {
                if (residual) {
                    float2 q0 = *(const float2*)(residual + (size_t)r0 * HW + col);
                    float2 q1 = *(const float2*)(residual + (size_t)r1 * HW + col);
                    v0.x += q0.x; v0.y += q0.y;
                    v1.x += q1.x; v1.y += q1.y;
                }
                *(float2*)(C + (size_t)r0 * HW + col) = v0;
                *(float2*)(C + (size_t)r1 * HW + col) = v1;
            } else {
                uint32_t h, l;
                bfsplit2(v0.x, v0.y, h, l);
                *(uint32_t*)(Ch + (size_t)r0 * HW + col) = h;
                *(uint32_t*)(Cl + (size_t)r0 * HW + col) = l;
                bfsplit2(v1.x, v1.y, h, l);
                *(uint32_t*)(Ch + (size_t)r1 * HW + col) = h;
                *(uint32_t*)(Cl + (size_t)r1 * HW + col) = l;
            }
        }
    }
}

// ---------------- merged feat transpose: all 4 levels, (N,C,HW) -> (N,HW,C) fp16 ----------------
__global__ void transpose_all_k(const float* __restrict__ f0, const float* __restrict__ f1,
                                const float* __restrict__ f2, const float* __restrict__ f3,
                                __half* __restrict__ out) {
    __shared__ float tile[32][33];
    int bx = blockIdx.x;
    const float* in;
    int hw, ooff, tx0;
    if (bx < 88)       { in = f0; hw = 2816; ooff = 0;     tx0 = bx; }
    else if (bx < 110) { in = f1; hw = 704;  ooff = 16896; tx0 = bx - 88; }
    else if (bx < 116) { in = f2; hw = 176;  ooff = 21120; tx0 = bx - 110; }
    else               { in = f3; hw = 44;   ooff = 22176; tx0 = bx - 116; }
    int n = blockIdx.z;
    int posBase = tx0 * 32;
    int cBase = blockIdx.y * 32;
    int x = posBase + threadIdx.x;
    for (int i = threadIdx.y; i < 32; i += 8) {
        int c = cBase + i;
        if (x < hw) tile[i][threadIdx.x] = in[((size_t)n * 128 + c) * hw + x];
    }
    __syncthreads();
    for (int i = threadIdx.y; i < 32; i += 8) {
        int pos = posBase + i;
        if (pos < hw)
            out[((size_t)(ooff + n * hw + pos)) * 128 + cBase + threadIdx.x] =
                __float2half(tile[threadIdx.x][i]);
    }
}

// ---------------- im2col -> bf16 h/l planes ----------------
__global__ void im2col_k(const float* __restrict__ in,
                         uint16_t* __restrict__ h, uint16_t* __restrict__ l) {
    int idx = blockIdx.x * 256 + threadIdx.x;    // total 1152*8192
    if (idx >= 1152 * 8192) return;
    int pix2 = (idx & 8191) * 2;
    int kcol = idx >> 13;
    int ci = kcol / 9;
    int t = kcol - ci * 9;
    int dy = t / 3 - 1, dx = t % 3 - 1;
    int y = (pix2 >> 7) + dy;
    int x = (pix2 & 127) + dx;
    float v0 = 0.f, v1 = 0.f;
    if ((unsigned)y < 128u) {
        if ((unsigned)x < 128u)       v0 = in[ci * 16384 + y * 128 + x];
        if ((unsigned)(x + 1) < 128u) v1 = in[ci * 16384 + y * 128 + x + 1];
    }
    uint32_t hh, ll;
    bfsplit2(v0, v1, hh, ll);
    size_t off = (size_t)kcol * 16384 + pix2;
    *(uint32_t*)(h + off) = hh;
    *(uint32_t*)(l + off) = ll;
}

// ---------------- instance norm per channel over 16384 spatial ----------------
__global__ void inorm_k(const float* __restrict__ in, float* __restrict__ out) {
    __shared__ float red[20];
    int c = blockIdx.x, tid = threadIdx.x;
    const float* row = in + (size_t)c * HW;
    float s = 0.f, q = 0.f;
    for (int i = tid; i < HW; i += 256) { float v = row[i]; s += v; q += v * v; }
#pragma unroll
    for (int o = 16; o; o >>= 1) { s += __shfl_down_sync(~0u, s, o); q += __shfl_down_sync(~0u, q, o); }
    if ((tid & 31) == 0) { red[tid >> 5] = s; red[8 + (tid >> 5)] = q; }
    __syncthreads();
    if (tid == 0) {
        float ts = 0.f, tq = 0.f;
        for (int w = 0; w < 8; w++) { ts += red[w]; tq += red[8 + w]; }
        float m = ts * (1.f / HW);
        red[16] = m;
        red[17] = rsqrtf(tq * (1.f / HW) - m * m + 1e-5f);
    }
    __syncthreads();
    float m = red[16], inv = red[17];
    for (int i = tid; i < HW; i += 256)
        out[(size_t)c * HW + i] = (row[i] - m) * inv;
}

// ---------------- offsets / scale-weights / pts / height (64 px per block) ----------------
__global__ void __launch_bounds__(256) stageB_k(
    const float* __restrict__ q1, const float* __restrict__ bev_pos,
    const float* __restrict__ off_w, const float* __restrict__ off_b,
    const float* __restrict__ sw_w, const float* __restrict__ sw_b,
    float* __restrict__ pts, float* __restrict__ swout, float* __restrict__ height)
{
    __shared__ float qs[128][64];
    __shared__ float sres[56][64];
    int tid = threadIdx.x;
    int pix0 = blockIdx.x * 64;

#pragma unroll
    for (int i = 0; i < 32; i++) {
        int idx = tid + i * 256;
        int c = idx >> 6, px = idx & 63;
        qs[c][px] = q1[(size_t)c * HW + pix0 + px];
    }
    __syncthreads();

#pragma unroll
    for (int i = 0; i < 14; i++) {
        int j = tid + i * 256;
        int px = j & 63, o = j >> 6;
        const float* wrow = (o < 24) ? (off_w + o * 128) : (sw_w + (o - 24) * 128);
        float a = (o < 24) ? off_b[o] : sw_b[o - 24];
#pragma unroll 8
        for (int k = 0; k < 128; k++) a = fmaf(wrow[k], qs[k][px], a);
        sres[o][px] = a;
    }
    __syncthreads();

#pragma unroll
    for (int i = 0; i < 2; i++) {
        int j = tid + i * 256;
        int px = j & 63, p = j >> 6;
        int pix = pix0 + px;
        const float LXY = 0.25f + 1e-6f, LZ = 4.0f + 1e-6f;
        float sx = 1.f / (1.f + expf(-sres[p * 3 + 0][px]));
        float sy = 1.f / (1.f + expf(-sres[p * 3 + 1][px]));
        float sz = 1.f / (1.f + expf(-sres[p * 3 + 2][px]));
        float ox = sx * 2.f * LXY - LXY;
        float oy = sy * 2.f * LXY - LXY;
        float oz = sz * 2.f * LZ - LZ;
        float rx = bev_pos[pix * 3 + 0] * 100.f - 50.f;
        float ry = bev_pos[pix * 3 + 1] * 100.f - 50.f;
        float rz = bev_pos[pix * 3 + 2] * 8.f - 4.f;
        pts[pix * 24 + p * 3 + 0] = rx + ox;
        pts[pix * 24 + p * 3 + 1] = ry + oy;
        pts[pix * 24 + p * 3 + 2] = rz + oz;
        height[p * HW + pix] = oz;
        float l0 = sres[24 + p * 4 + 0][px], l1 = sres[24 + p * 4 + 1][px];
        float l2 = sres[24 + p * 4 + 2][px], l3 = sres[24 + p * 4 + 3][px];
        float mx = fmaxf(fmaxf(l0, l1), fmaxf(l2, l3));
        float e0 = expf(l0 - mx), e1 = expf(l1 - mx), e2 = expf(l2 - mx), e3 = expf(l3 - mx);
        float inv = 1.f / (e0 + e1 + e2 + e3);
        swout[pix * 32 + p * 4 + 0] = e0 * inv;
        swout[pix * 32 + p * 4 + 1] = e1 * inv;
        swout[pix * 32 + p * 4 + 2] = e2 * inv;
        swout[pix * 32 + p * 4 + 3] = e3 * inv;
    }
}

// ---------------- fused projection + bilinear sampling (fp16 feats) + PE MLP ----------------
__global__ void __launch_bounds__(128) sample_k(
    const float* __restrict__ pts, const float* __restrict__ sww,
    const float* __restrict__ l2i,
    const float* __restrict__ pe_w1, const float* __restrict__ pe_b1,
    const float* __restrict__ pe_w2, const float* __restrict__ pe_b2,
    uint16_t* __restrict__ outh, uint16_t* __restrict__ outl)
{
    const int PIX = 16;
    __shared__ float sM[72];
    __shared__ float sPts[PIX][3];
    __shared__ float sSw[PIX][4];
    __shared__ float sH[256][PIX];
    __shared__ float sOut[PIX][133];

    int p = blockIdx.y;
    int pix0 = blockIdx.x * PIX;
    int tid = threadIdx.x;

    if (tid < 72) sM[tid] = l2i[(tid / 12) * 16 + (tid % 12)];
    if (tid < PIX) {
        int pix = pix0 + tid;
        sPts[tid][0] = pts[pix * 24 + p * 3 + 0];
        sPts[tid][1] = pts[pix * 24 + p * 3 + 1];
        sPts[tid][2] = pts[pix * 24 + p * 3 + 2];
    } else if (tid < 2 * PIX) {
        int s = tid - PIX;
        int pix = pix0 + s;
        sSw[s][0] = sww[pix * 32 + p * 4 + 0];
        sSw[s][1] = sww[pix * 32 + p * 4 + 1];
        sSw[s][2] = sww[pix * 32 + p * 4 + 2];
        sSw[s][3] = sww[pix * 32 + p * 4 + 3];
    }
    __syncthreads();

    for (int j = tid; j < PIX * 256; j += 128) {
        int s = j & (PIX - 1);
        int j2 = j >> 4;
        float xn = (sPts[s][0] + 50.f) * 0.01f;
        float yn = (sPts[s][1] + 50.f) * 0.01f;
        float zn = (sPts[s][2] + 4.f) * 0.125f;
        float h = pe_b1[j2] + xn * pe_w1[j2] + yn * pe_w1[256 + j2] + zn * pe_w1[512 + j2];
        sH[j2][s] = fmaxf(h, 0.f);
    }
    __syncthreads();

    int warp = tid >> 5, lane = tid & 31;
    const int HS[4] = {32, 16, 8, 4};
    const int WS[4] = {88, 44, 22, 11};
    const int OFF[4] = {0, 16896, 21120, 22176};

    float4 accp[4];
#pragma unroll
    for (int pp = 0; pp < 4; pp++) accp[pp] = *(const float4*)(pe_b2 + lane * 4);
    for (int j2 = 0; j2 < 256; j2++) {
        float4 w = *(const float4*)(pe_w2 + j2 * 128 + lane * 4);
#pragma unroll
        for (int pp = 0; pp < 4; pp++) {
            float hv = sH[j2][warp * 4 + pp];
            accp[pp].x = fmaf(hv, w.x, accp[pp].x);
            accp[pp].y = fmaf(hv, w.y, accp[pp].y);
            accp[pp].z = fmaf(hv, w.z, accp[pp].z);
            accp[pp].w = fmaf(hv, w.w, accp[pp].w);
        }
    }

#define TAP(texidx, wgt) do { \
    uint2 tv = *(const uint2*)(g_ftr + (size_t)(texidx) * 128 + lane * 4); \
    float2 a01 = __half22float2(*reinterpret_cast<const __half2*>(&tv.x)); \
    float2 a23 = __half22float2(*reinterpret_cast<const __half2*>(&tv.y)); \
    acc.x = fmaf((wgt), a01.x, acc.x); acc.y = fmaf((wgt), a01.y, acc.y); \
    acc.z = fmaf((wgt), a23.x, acc.z); acc.w = fmaf((wgt), a23.y, acc.w); \
} while (0)

    for (int it = 0; it < 4; it++) {
        int pl = warp * 4 + it;
        float X = sPts[pl][0], Y = sPts[pl][1], Z = sPts[pl][2];
        float4 acc = accp[it];
        float swl[4] = {sSw[pl][0], sSw[pl][1], sSw[pl][2], sSw[pl][3]};

        for (int n = 0; n < NCAM; n++) {
            const float* M = sM + n * 12;
            float cx = M[0] * X + M[1] * Y + M[2] * Z + M[3];
            float cy = M[4] * X + M[5] * Y + M[6] * Z + M[7];
            float cz = M[8] * X + M[9] * Y + M[10] * Z + M[11];
            if (cz <= 1e-5f) continue;
            float u = cx / cz * (1.f / 704.f);
            float v = cy / cz * (1.f / 256.f);
#pragma unroll
            for (int l = 0; l < 4; l++) {
                int Wl = WS[l], Hl = HS[l];
                float pxf = u * (float)Wl - 0.5f;
                float pyf = v * (float)Hl - 0.5f;
                float fx = floorf(pxf), fy = floorf(pyf);
                int x0 = (int)fx, y0 = (int)fy;
                if (x0 >= Wl || y0 >= Hl || x0 < -1 || y0 < -1) continue;
                float wx = pxf - fx, wy = pyf - fy;
                float g = swl[l];
                int base = OFF[l] + n * Hl * Wl;
                bool xl = (x0 >= 0), xr = (x0 + 1 < Wl);
                bool yt = (y0 >= 0), yb = (y0 + 1 < Hl);
                if (xl && yt) TAP(base + y0 * Wl + x0,           g * (1.f - wx) * (1.f - wy));
                if (xr && yt) TAP(base + y0 * Wl + x0 + 1,       g * wx * (1.f - wy));
                if (xl && yb) TAP(base + (y0 + 1) * Wl + x0,     g * (1.f - wx) * wy);
                if (xr && yb) TAP(base + (y0 + 1) * Wl + x0 + 1, g * wx * wy);
            }
        }
        sOut[pl][lane * 4 + 0] = acc.x;
        sOut[pl][lane * 4 + 1] = acc.y;
        sOut[pl][lane * 4 + 2] = acc.z;
        sOut[pl][lane * 4 + 3] = acc.w;
    }
    __syncthreads();
    for (int j = tid; j < PIX * 64; j += 128) {
        int c = j >> 3;
        int px = (j & 7) * 2;
        uint32_t h, l;
        bfsplit2(sOut[px][c], sOut[px + 1][c], h, l);
        size_t addr = ((size_t)(p * 128 + c)) * HW + pix0 + px;
        *(uint32_t*)(outh + addr) = h;
        *(uint32_t*)(outl + addr) = l;
    }
}

// ---------------- host launch ----------------
static void launch_tgemm(int M, int K,
                         const uint16_t* Ah, const uint16_t* Al,
                         const uint16_t* Bh, const uint16_t* Bl,
                         float* C, uint16_t* Ch, uint16_t* Cl,
                         const float* bias, const float* residual, int act) {
    static int attr_set = 0;
    if (!attr_set) {
        cudaFuncSetAttribute(tgemm_k, cudaFuncAttributeMaxDynamicSharedMemorySize, TG_DSMEM);
        attr_set = 1;
    }
    tgemm_k<<<dim3(128, M / 128), 256, TG_DSMEM>>>(M, K, Ah, Al, Bh, Bl, C, Ch, Cl, bias, residual, act);
}

extern "C" void kernel_launch(void* const* d_in, const int* in_sizes, int n_in,
                              void* d_out, int out_size) {
    const float* feat[4] = {(const float*)d_in[0], (const float*)d_in[1],
                            (const float*)d_in[2], (const float*)d_in[3]};
    const float* l2i = (const float*)d_in[4];
    const float* bev_query = (const float*)d_in[5];
    const float* bev_pos = (const float*)d_in[6];
    const float* in_w = (const float*)d_in[7];
    const float* in_b = (const float*)d_in[8];
    const float* off_w = (const float*)d_in[9];
    const float* off_b = (const float*)d_in[10];
    const float* sw_w = (const float*)d_in[11];
    const float* sw_b = (const float*)d_in[12];
    const float* pe_w1 = (const float*)d_in[13];
    const float* pe_b1 = (const float*)d_in[14];
    const float* pe_w2 = (const float*)d_in[15];
    const float* pe_b2 = (const float*)d_in[16];
    const float* mid_w1 = (const float*)d_in[17];
    const float* mid_b1 = (const float*)d_in[18];
    const float* mid_w2 = (const float*)d_in[19];
    const float* mid_b2 = (const float*)d_in[20];
    const float* mid_w3 = (const float*)d_in[21];
    const float* mid_b3 = (const float*)d_in[22];
    const float* out_w = (const float*)d_in[23];
    const float* out_b = (const float*)d_in[24];
    float* out = (float*)d_out;

    float *col, *y, *q1, *q2, *ptsb, *swb, *asf, *m1, *m2;
    __half* ftr;
    uint16_t* wsp;
    cudaGetSymbolAddress((void**)&ftr, g_ftr);
    cudaGetSymbolAddress((void**)&col, g_col);
    cudaGetSymbolAddress((void**)&y, g_y);
    cudaGetSymbolAddress((void**)&q1, g_q1);
    cudaGetSymbolAddress((void**)&q2, g_q2);
    cudaGetSymbolAddress((void**)&ptsb, g_pts);
    cudaGetSymbolAddress((void**)&swb, g_swm);
    cudaGetSymbolAddress((void**)&asf, g_asf);
    cudaGetSymbolAddress((void**)&m1, g_m1);
    cudaGetSymbolAddress((void**)&m2, g_m2);
    cudaGetSymbolAddress((void**)&wsp, g_wsp);

    uint16_t* colh = (uint16_t*)col;            uint16_t* coll = colh + (size_t)1152 * 16384;
    uint16_t* asfh = (uint16_t*)asf;            uint16_t* asfl = asfh + (size_t)1024 * 16384;
    uint16_t* m1h  = (uint16_t*)m1;             uint16_t* m1l  = m1h  + (size_t)512 * 16384;
    uint16_t* m2h  = (uint16_t*)m2;             uint16_t* m2l  = m2h  + (size_t)512 * 16384;
    const size_t WTOT = 1146880;
    uint16_t* w_in_h  = wsp;                    uint16_t* w_in_l  = wsp + WTOT;
    uint16_t* w_m1_h  = wsp + 147456;           uint16_t* w_m1_l  = w_m1_h + WTOT;
    uint16_t* w_m2_h  = wsp + 671744;           uint16_t* w_m2_l  = w_m2_h + WTOT;
    uint16_t* w_m3_h  = wsp + 933888;           uint16_t* w_m3_l  = w_m3_h + WTOT;
    uint16_t* w_out_h = wsp + 999424;           uint16_t* w_out_l = w_out_h + WTOT;

    // 0. pre-split all weights (one launch)
    wsplit_all_k<<<2240, 256>>>(in_w, mid_w1, mid_w2, mid_w3, out_w, wsp);

    // 1. transpose feats to channel-last fp16 (one launch, all levels)
    transpose_all_k<<<dim3(118, 4, 6), dim3(32, 8)>>>(feat[0], feat[1], feat[2], feat[3], ftr);

    // 2. conv_in + residual -> y ; inorm -> q1
    im2col_k<<<(1152 * 8192) / 256, 256>>>(bev_query, colh, coll);
    launch_tgemm(128, 1152, w_in_h, w_in_l, colh, coll, y, nullptr, nullptr, in_b, bev_query, 0);
    inorm_k<<<128, 256>>>(y, q1);

    // 3. offsets / scale weights / pts / height
    stageB_k<<<256, 256>>>(q1, bev_pos, off_w, off_b, sw_w, sw_b, ptsb, swb, out + 128 * HW);

    // 4. sampling + PE -> asf bf16 planes
    sample_k<<<dim3(1024, 8), 128>>>(ptsb, swb, l2i, pe_w1, pe_b1, pe_w2, pe_b2, asfh, asfl);

    // 5. mid MLP chain
    launch_tgemm(512, 1024, w_m1_h, w_m1_l, asfh, asfl, nullptr, m1h, m1l, mid_b1, nullptr, 1);
    launch_tgemm(512,  512, w_m2_h, w_m2_l, m1h,  m1l,  nullptr, m2h, m2l, mid_b2, nullptr, 1);
    launch_tgemm(128,  512, w_m3_h, w_m3_l, m2h,  m2l,  y, nullptr, nullptr, mid_b3, q1, 0);
    inorm_k<<<128, 256>>>(y, q2);

    // 6. conv_out + residual ; final inorm -> d_out (q)
    im2col_k<<<(1152 * 8192) / 256, 256>>>(q2, colh, coll);
    launch_tgemm(128, 1152, w_out_h, w_out_l, colh, coll, y, nullptr, nullptr, out_b, q2, 0);
    inorm_k<<<128, 256>>>(y, out);
}

// round 15
// speedup vs baseline: 1.1000x; 1.0468x over previous
#include <cuda_runtime.h>
#include <cuda_bf16.h>
#include <cuda_fp16.h>
#include <math.h>
#include <stdint.h>

#define HW 16384   // 128x128 BEV
#define NCAM 6
#define QP_PITCH 144
#define QP_CH    18720           // 130 * 144
#define QP_PLANE 2396160         // 128 * 18720

// ---------------- scratch (static device allocations; no cudaMalloc) ----------------
__device__ __half g_ftr[22440 * 128];       // feats transposed channel-last, fp16
__device__ uint16_t g_qsp[2 * 3 * QP_PLANE]; // padded shifted q planes: [h/l][dx][c][yy][xx]
__device__ float g_y[128 * 16384];          // pre-norm accumulator (reused)
__device__ float g_q1[128 * 16384];
__device__ float g_q2[128 * 16384];
__device__ float g_pts[16384 * 24];
__device__ float g_swm[16384 * 32];
__device__ float g_asf[1024 * 16384];       // h/l bf16 planes
__device__ float g_m1[512 * 16384];         // h/l bf16 planes
__device__ float g_m2[512 * 16384];         // h/l bf16 planes
__device__ uint16_t g_wsp[2 * 1146880];     // pre-split weights (h plane, then l plane)

// ---------------- helpers ----------------
__device__ __forceinline__ float gelu_exact(float x) { return x * normcdff(x); }

__device__ __forceinline__ uint32_t smem_to_u32(const void* p) {
    uint32_t a;
    asm("{ .reg .u64 t; cvta.to.shared.u64 t, %1; cvt.u32.u64 %0, t; }" : "=r"(a) : "l"(p));
    return a;
}

__device__ __forceinline__ void bfsplit2(float a, float b, uint32_t& h, uint32_t& l) {
    __nv_bfloat162 hb = __floats2bfloat162_rn(a, b);
    float ra = a - __bfloat162float(hb.x);
    float rb = b - __bfloat162float(hb.y);
    __nv_bfloat162 lb = __floats2bfloat162_rn(ra, rb);
    h = *reinterpret_cast<uint32_t*>(&hb);
    l = *reinterpret_cast<uint32_t*>(&lb);
}

__device__ __forceinline__ void ldsm_x4(uint32_t addr, uint32_t& r0, uint32_t& r1, uint32_t& r2, uint32_t& r3) {
    asm volatile("ldmatrix.sync.aligned.m8n8.x4.shared.b16 {%0,%1,%2,%3}, [%4];"
                 : "=r"(r0), "=r"(r1), "=r"(r2), "=r"(r3) : "r"(addr));
}
__device__ __forceinline__ void ldsm_x4_t(uint32_t addr, uint32_t& r0, uint32_t& r1, uint32_t& r2, uint32_t& r3) {
    asm volatile("ldmatrix.sync.aligned.m8n8.x4.trans.shared.b16 {%0,%1,%2,%3}, [%4];"
                 : "=r"(r0), "=r"(r1), "=r"(r2), "=r"(r3) : "r"(addr));
}
__device__ __forceinline__ void mma16816(float* d, const uint32_t* a, const uint32_t* b) {
    asm volatile("mma.sync.aligned.m16n8k16.row.col.f32.bf16.bf16.f32 "
                 "{%0,%1,%2,%3}, {%4,%5,%6,%7}, {%8,%9}, {%0,%1,%2,%3};"
                 : "+f"(d[0]), "+f"(d[1]), "+f"(d[2]), "+f"(d[3])
                 : "r"(a[0]), "r"(a[1]), "r"(a[2]), "r"(a[3]), "r"(b[0]), "r"(b[1]));
}

#define CP16(dst, src) \
    asm volatile("cp.async.cg.shared.global [%0], [%1], 16;" :: "r"(dst), "l"(src) : "memory")
#define CP_COMMIT() asm volatile("cp.async.commit_group;" ::: "memory")
#define CP_WAITG0() asm volatile("cp.async.wait_group 0;" ::: "memory")
#define CP_WAITG1() asm volatile("cp.async.wait_group 1;" ::: "memory")

// ---------------- merged weight pre-split (conv weights permuted to k = tap*128 + ic) ----------------
__global__ void wsplit_all_k(const float* __restrict__ w_in, const float* __restrict__ w1,
                             const float* __restrict__ w2, const float* __restrict__ w3,
                             const float* __restrict__ w_out, uint16_t* __restrict__ wsp) {
    int i = blockIdx.x * 256 + threadIdx.x;      // global pair index, total 573440
    const float* src;
    size_t pbase;
    int local;
    int isconv = 0;
    if (i < 73728)       { src = w_in;  pbase = 0;      local = i; isconv = 1; }
    else if (i < 335872) { src = w1;    pbase = 147456; local = i - 73728; }
    else if (i < 466944) { src = w2;    pbase = 671744; local = i - 335872; }
    else if (i < 499712) { src = w3;    pbase = 933888; local = i - 466944; }
    else                 { src = w_out; pbase = 999424; local = i - 499712; isconv = 1; }
    float va, vb;
    if (isconv) {
        // dest k-order: kk = tap*128 + ic ; source k-order: ic*9 + tap
        int e0 = local * 2;
        int o = e0 / 1152, kk = e0 - o * 1152;
        int tap = kk >> 7, ic = kk & 127;
        va = src[o * 1152 + ic * 9 + tap];
        vb = src[o * 1152 + (ic + 1) * 9 + tap];
    } else {
        float2 v = *(const float2*)(src + (size_t)local * 2);
        va = v.x; vb = v.y;
    }
    uint32_t hh, ll;
    bfsplit2(va, vb, hh, ll);
    *(uint32_t*)(wsp + pbase + (size_t)local * 2) = hh;
    *(uint32_t*)(wsp + 1146880 + pbase + (size_t)local * 2) = ll;
}

// ---------------- q pre-split into padded, dx-shifted bf16 planes ----------------
// plane_dx[c][yy][xx] = q[c][yy-1][xx-8+dx] (zero where out of range)
__global__ void qsplit_k(const float* __restrict__ q,
                         uint16_t* __restrict__ ph, uint16_t* __restrict__ pl) {
    int idx = blockIdx.x * 256 + threadIdx.x;   // c*130*72 + yy*72 + xx2
    if (idx >= 128 * 130 * 72) return;
    int xx2 = idx % 72;
    int t2 = idx / 72;
    int yy = t2 % 130;
    int c = t2 / 130;
    int y = yy - 1;
    int xx0 = xx2 * 2;
#pragma unroll
    for (int dxp = 0; dxp < 3; dxp++) {
        int x0 = xx0 - 8 + (dxp - 1);
        float v0 = 0.f, v1 = 0.f;
        if ((unsigned)y < 128u) {
            if ((unsigned)x0 < 128u)       v0 = q[c * 16384 + y * 128 + x0];
            if ((unsigned)(x0 + 1) < 128u) v1 = q[c * 16384 + y * 128 + x0 + 1];
        }
        uint32_t h, l;
        bfsplit2(v0, v1, h, l);
        size_t off = (size_t)dxp * QP_PLANE + (size_t)c * QP_CH + yy * QP_PITCH + xx0;
        *(uint32_t*)(ph + off) = h;
        *(uint32_t*)(pl + off) = l;
    }
}

// ---------------- warp-MMA bf16-split GEMM (3-stage cp.async pipeline, implicit-conv mode) ----------------
#define A_PITCH 80
#define B_PITCH 272
#define AH_OFF 0
#define AL_OFF 10240
#define BH_OFF 20480
#define BL_OFF 29184
#define STG 37888
#define TG_DSMEM (3 * STG + 1024)

__global__ void __launch_bounds__(256, 2) tgemm_k(
    int M, int K, int conv,
    const uint16_t* __restrict__ Ah, const uint16_t* __restrict__ Al,
    const uint16_t* __restrict__ Bh, const uint16_t* __restrict__ Bl,
    float* __restrict__ C, uint16_t* __restrict__ Ch, uint16_t* __restrict__ Cl,
    const float* __restrict__ bias, const float* __restrict__ residual, int act)
{
    extern __shared__ char dsm[];
    uint32_t dynu = smem_to_u32(dsm);
    uint32_t base = (dynu + 1023u) & ~1023u;

    int tid = threadIdx.x;
    int lane = tid & 31, warp = tid >> 5;
    int wm = warp & 1, wn = warp >> 1;
    int pix0 = blockIdx.x * 128;
    int rowA = blockIdx.y * 128;

    float acc[4][4][4];
#pragma unroll
    for (int i = 0; i < 4; i++)
#pragma unroll
        for (int j = 0; j < 4; j++)
#pragma unroll
            for (int q = 0; q < 4; q++) acc[i][j][q] = 0.f;

#define ISSUE(t, buf) do { \
    uint32_t s = base + (buf) * STG; \
    int k0 = (t) << 5; \
    _Pragma("unroll") \
    for (int i = 0; i < 2; i++) { \
        int c = tid * 2 + i; \
        int ar = c >> 2, akc = c & 3; \
        size_t aoff = (size_t)(rowA + ar) * K + k0 + akc * 8; \
        uint32_t da = s + AH_OFF + ar * A_PITCH + akc * 16; \
        CP16(da, Ah + aoff); \
        CP16(da + (AL_OFF - AH_OFF), Al + aoff); \
        int br = c >> 4, bnc = c & 15; \
        size_t boff; \
        if (conv) { \
            int tap = k0 >> 7; \
            int dy = tap / 3 - 1, dxp = tap - (tap / 3) * 3; \
            int ch = (k0 & 127) + br; \
            int yy = (int)blockIdx.x + dy + 1; \
            boff = (size_t)dxp * QP_PLANE + (size_t)ch * QP_CH + (size_t)yy * QP_PITCH + 8 + bnc * 8; \
        } else { \
            boff = (size_t)(k0 + br) * HW + pix0 + bnc * 8; \
        } \
        uint32_t db = s + BH_OFF + br * B_PITCH + bnc * 16; \
        CP16(db, Bh + boff); \
        CP16(db + (BL_OFF - BH_OFF), Bl + boff); \
    } \
    CP_COMMIT(); \
} while (0)

    int nt = K >> 5;
    ISSUE(0, 0);
    ISSUE(1, 1);            // nt >= 16 always here

    int cur = 0, ahead = 2;
    for (int t = 0; t < nt; t++) {
        if (t + 1 < nt) { CP_WAITG1(); } else { CP_WAITG0(); }
        __syncthreads();     // group t visible to all; all compute(t-1) done before slot reuse
        if (t + 2 < nt) ISSUE(t + 2, ahead);

        uint32_t sbase = base + cur * STG;
#pragma unroll
        for (int kk = 0; kk < 2; kk++) {
            uint32_t bh[4][2], bl[4][2];
#pragma unroll
            for (int nj2 = 0; nj2 < 2; nj2++) {
                uint32_t addrh = sbase + BH_OFF + ((lane & 15) + kk * 16) * B_PITCH
                               + wn * 64 + nj2 * 32 + (lane >> 4) * 16;
                ldsm_x4_t(addrh, bh[nj2 * 2][0], bh[nj2 * 2][1], bh[nj2 * 2 + 1][0], bh[nj2 * 2 + 1][1]);
                ldsm_x4_t(addrh + (BL_OFF - BH_OFF),
                          bl[nj2 * 2][0], bl[nj2 * 2][1], bl[nj2 * 2 + 1][0], bl[nj2 * 2 + 1][1]);
            }
#pragma unroll
            for (int mi = 0; mi < 4; mi++) {
                uint32_t ah[4], al[4];
                uint32_t addr = sbase + AH_OFF + (wm * 64 + mi * 16 + (lane & 15)) * A_PITCH
                              + kk * 32 + (lane >> 4) * 16;
                ldsm_x4(addr, ah[0], ah[1], ah[2], ah[3]);
                ldsm_x4(addr + (AL_OFF - AH_OFF), al[0], al[1], al[2], al[3]);
#pragma unroll
                for (int nj = 0; nj < 4; nj++) {
                    mma16816(acc[mi][nj], ah, bh[nj]);
                    mma16816(acc[mi][nj], ah, bl[nj]);
                    mma16816(acc[mi][nj], al, bh[nj]);
                }
            }
        }
        cur = (cur == 2) ? 0 : cur + 1;
        ahead = (ahead == 2) ? 0 : ahead + 1;
    }

#pragma unroll
    for (int mi = 0; mi < 4; mi++) {
        int r0 = rowA + wm * 64 + mi * 16 + (lane >> 2);
        int r1 = r0 + 8;
        float b0 = bias[r0], b1 = bias[r1];
#pragma unroll
        for (int nj = 0; nj < 4; nj++) {
            int col = pix0 + wn * 32 + nj * 8 + (lane & 3) * 2;
            float2 v0, v1;
            v0.x = acc[mi][nj][0] + b0; v0.y = acc[mi][nj][1] + b0;
            v1.x = acc[mi][nj][2] + b1; v1.y = acc[mi][nj][3] + b1;
            if (act) {
                v0.x = gelu_exact(v0.x); v0.y = gelu_exact(v0.y);
                v1.x = gelu_exact(v1.x); v1.y = gelu_exact(v1.y);
            }
            if (C) {
                if (residual) {
                    float2 q0 = *(const float2*)(residual + (size_t)r0 * HW + col);
                    float2 q1 = *(const float2*)(residual + (size_t)r1 * HW + col);
                    v0.x += q0.x; v0.y += q0.y;
                    v1.x += q1.x; v1.y += q1.y;
                }
                *(float2*)(C + (size_t)r0 * HW + col) = v0;
                *(float2*)(C + (size_t)r1 * HW + col) = v1;
            } else {
                uint32_t h, l;
                bfsplit2(v0.x, v0.y, h, l);
                *(uint32_t*)(Ch + (size_t)r0 * HW + col) = h;
                *(uint32_t*)(Cl + (size_t)r0 * HW + col) = l;
                bfsplit2(v1.x, v1.y, h, l);
                *(uint32_t*)(Ch + (size_t)r1 * HW + col) = h;
                *(uint32_t*)(Cl + (size_t)r1 * HW + col) = l;
            }
        }
    }
}

// ---------------- merged feat transpose: all 4 levels, (N,C,HW) -> (N,HW,C) fp16 ----------------
__global__ void transpose_all_k(const float* __restrict__ f0, const float* __restrict__ f1,
                                const float* __restrict__ f2, const float* __restrict__ f3,
                                __half* __restrict__ out) {
    __shared__ float tile[32][33];
    int bx = blockIdx.x;
    const float* in;
    int hw, ooff, tx0;
    if (bx < 88)       { in = f0; hw = 2816; ooff = 0;     tx0 = bx; }
    else if (bx < 110) { in = f1; hw = 704;  ooff = 16896; tx0 = bx - 88; }
    else if (bx < 116) { in = f2; hw = 176;  ooff = 21120; tx0 = bx - 110; }
    else               { in = f3; hw = 44;   ooff = 22176; tx0 = bx - 116; }
    int n = blockIdx.z;
    int posBase = tx0 * 32;
    int cBase = blockIdx.y * 32;
    int x = posBase + threadIdx.x;
    for (int i = threadIdx.y; i < 32; i += 8) {
        int c = cBase + i;
        if (x < hw) tile[i][threadIdx.x] = in[((size_t)n * 128 + c) * hw + x];
    }
    __syncthreads();
    for (int i = threadIdx.y; i < 32; i += 8) {
        int pos = posBase + i;
        if (pos < hw)
            out[((size_t)(ooff + n * hw + pos)) * 128 + cBase + threadIdx.x] =
                __float2half(tile[threadIdx.x][i]);
    }
}

// ---------------- instance norm per channel over 16384 spatial ----------------
__global__ void inorm_k(const float* __restrict__ in, float* __restrict__ out) {
    __shared__ float red[20];
    int c = blockIdx.x, tid = threadIdx.x;
    const float* row = in + (size_t)c * HW;
    float s = 0.f, q = 0.f;
    for (int i = tid; i < HW; i += 256) { float v = row[i]; s += v; q += v * v; }
#pragma unroll
    for (int o = 16; o; o >>= 1) { s += __shfl_down_sync(~0u, s, o); q += __shfl_down_sync(~0u, q, o); }
    if ((tid & 31) == 0) { red[tid >> 5] = s; red[8 + (tid >> 5)] = q; }
    __syncthreads();
    if (tid == 0) {
        float ts = 0.f, tq = 0.f;
        for (int w = 0; w < 8; w++) { ts += red[w]; tq += red[8 + w]; }
        float m = ts * (1.f / HW);
        red[16] = m;
        red[17] = rsqrtf(tq * (1.f / HW) - m * m + 1e-5f);
    }
    __syncthreads();
    float m = red[16], inv = red[17];
    for (int i = tid; i < HW; i += 256)
        out[(size_t)c * HW + i] = (row[i] - m) * inv;
}

// ---------------- offsets / scale-weights / pts / height (64 px per block) ----------------
__global__ void __launch_bounds__(256) stageB_k(
    const float* __restrict__ q1, const float* __restrict__ bev_pos,
    const float* __restrict__ off_w, const float* __restrict__ off_b,
    const float* __restrict__ sw_w, const float* __restrict__ sw_b,
    float* __restrict__ pts, float* __restrict__ swout, float* __restrict__ height)
{
    __shared__ float qs[128][64];
    __shared__ float sres[56][64];
    int tid = threadIdx.x;
    int pix0 = blockIdx.x * 64;

#pragma unroll
    for (int i = 0; i < 32; i++) {
        int idx = tid + i * 256;
        int c = idx >> 6, px = idx & 63;
        qs[c][px] = q1[(size_t)c * HW + pix0 + px];
    }
    __syncthreads();

#pragma unroll
    for (int i = 0; i < 14; i++) {
        int j = tid + i * 256;
        int px = j & 63, o = j >> 6;
        const float* wrow = (o < 24) ? (off_w + o * 128) : (sw_w + (o - 24) * 128);
        float a = (o < 24) ? off_b[o] : sw_b[o - 24];
#pragma unroll 8
        for (int k = 0; k < 128; k++) a = fmaf(wrow[k], qs[k][px], a);
        sres[o][px] = a;
    }
    __syncthreads();

#pragma unroll
    for (int i = 0; i < 2; i++) {
        int j = tid + i * 256;
        int px = j & 63, p = j >> 6;
        int pix = pix0 + px;
        const float LXY = 0.25f + 1e-6f, LZ = 4.0f + 1e-6f;
        float sx = 1.f / (1.f + expf(-sres[p * 3 + 0][px]));
        float sy = 1.f / (1.f + expf(-sres[p * 3 + 1][px]));
        float sz = 1.f / (1.f + expf(-sres[p * 3 + 2][px]));
        float ox = sx * 2.f * LXY - LXY;
        float oy = sy * 2.f * LXY - LXY;
        float oz = sz * 2.f * LZ - LZ;
        float rx = bev_pos[pix * 3 + 0] * 100.f - 50.f;
        float ry = bev_pos[pix * 3 + 1] * 100.f - 50.f;
        float rz = bev_pos[pix * 3 + 2] * 8.f - 4.f;
        pts[pix * 24 + p * 3 + 0] = rx + ox;
        pts[pix * 24 + p * 3 + 1] = ry + oy;
        pts[pix * 24 + p * 3 + 2] = rz + oz;
        height[p * HW + pix] = oz;
        float l0 = sres[24 + p * 4 + 0][px], l1 = sres[24 + p * 4 + 1][px];
        float l2 = sres[24 + p * 4 + 2][px], l3 = sres[24 + p * 4 + 3][px];
        float mx = fmaxf(fmaxf(l0, l1), fmaxf(l2, l3));
        float e0 = expf(l0 - mx), e1 = expf(l1 - mx), e2 = expf(l2 - mx), e3 = expf(l3 - mx);
        float inv = 1.f / (e0 + e1 + e2 + e3);
        swout[pix * 32 + p * 4 + 0] = e0 * inv;
        swout[pix * 32 + p * 4 + 1] = e1 * inv;
        swout[pix * 32 + p * 4 + 2] = e2 * inv;
        swout[pix * 32 + p * 4 + 3] = e3 * inv;
    }
}

// ---------------- fused projection + bilinear sampling (fp16 feats) + PE MLP ----------------
__global__ void __launch_bounds__(128) sample_k(
    const float* __restrict__ pts, const float* __restrict__ sww,
    const float* __restrict__ l2i,
    const float* __restrict__ pe_w1, const float* __restrict__ pe_b1,
    const float* __restrict__ pe_w2, const float* __restrict__ pe_b2,
    uint16_t* __restrict__ outh, uint16_t* __restrict__ outl)
{
    const int PIX = 16;
    __shared__ float sM[72];
    __shared__ float sPts[PIX][3];
    __shared__ float sSw[PIX][4];
    __shared__ float sH[256][PIX];
    __shared__ float sOut[PIX][133];

    int p = blockIdx.y;
    int pix0 = blockIdx.x * PIX;
    int tid = threadIdx.x;

    if (tid < 72) sM[tid] = l2i[(tid / 12) * 16 + (tid % 12)];
    if (tid < PIX) {
        int pix = pix0 + tid;
        sPts[tid][0] = pts[pix * 24 + p * 3 + 0];
        sPts[tid][1] = pts[pix * 24 + p * 3 + 1];
        sPts[tid][2] = pts[pix * 24 + p * 3 + 2];
    } else if (tid < 2 * PIX) {
        int s = tid - PIX;
        int pix = pix0 + s;
        sSw[s][0] = sww[pix * 32 + p * 4 + 0];
        sSw[s][1] = sww[pix * 32 + p * 4 + 1];
        sSw[s][2] = sww[pix * 32 + p * 4 + 2];
        sSw[s][3] = sww[pix * 32 + p * 4 + 3];
    }
    __syncthreads();

    for (int j = tid; j < PIX * 256; j += 128) {
        int s = j & (PIX - 1);
        int j2 = j >> 4;
        float xn = (sPts[s][0] + 50.f) * 0.01f;
        float yn = (sPts[s][1] + 50.f) * 0.01f;
        float zn = (sPts[s][2] + 4.f) * 0.125f;
        float h = pe_b1[j2] + xn * pe_w1[j2] + yn * pe_w1[256 + j2] + zn * pe_w1[512 + j2];
        sH[j2][s] = fmaxf(h, 0.f);
    }
    __syncthreads();

    int warp = tid >> 5, lane = tid & 31;
    const int HS[4] = {32, 16, 8, 4};
    const int WS[4] = {88, 44, 22, 11};
    const int OFF[4] = {0, 16896, 21120, 22176};

    float4 accp[4];
#pragma unroll
    for (int pp = 0; pp < 4; pp++) accp[pp] = *(const float4*)(pe_b2 + lane * 4);
    for (int j2 = 0; j2 < 256; j2++) {
        float4 w = *(const float4*)(pe_w2 + j2 * 128 + lane * 4);
#pragma unroll
        for (int pp = 0; pp < 4; pp++) {
            float hv = sH[j2][warp * 4 + pp];
            accp[pp].x = fmaf(hv, w.x, accp[pp].x);
            accp[pp].y = fmaf(hv, w.y, accp[pp].y);
            accp[pp].z = fmaf(hv, w.z, accp[pp].z);
            accp[pp].w = fmaf(hv, w.w, accp[pp].w);
        }
    }

#define TAP(texidx, wgt) do { \
    uint2 tv = *(const uint2*)(g_ftr + (size_t)(texidx) * 128 + lane * 4); \
    float2 a01 = __half22float2(*reinterpret_cast<const __half2*>(&tv.x)); \
    float2 a23 = __half22float2(*reinterpret_cast<const __half2*>(&tv.y)); \
    acc.x = fmaf((wgt), a01.x, acc.x); acc.y = fmaf((wgt), a01.y, acc.y); \
    acc.z = fmaf((wgt), a23.x, acc.z); acc.w = fmaf((wgt), a23.y, acc.w); \
} while (0)

    for (int it = 0; it < 4; it++) {
        int pl = warp * 4 + it;
        float X = sPts[pl][0], Y = sPts[pl][1], Z = sPts[pl][2];
        float4 acc = accp[it];
        float swl[4] = {sSw[pl][0], sSw[pl][1], sSw[pl][2], sSw[pl][3]};

        for (int n = 0; n < NCAM; n++) {
            const float* M = sM + n * 12;
            float cx = M[0] * X + M[1] * Y + M[2] * Z + M[3];
            float cy = M[4] * X + M[5] * Y + M[6] * Z + M[7];
            float cz = M[8] * X + M[9] * Y + M[10] * Z + M[11];
            if (cz <= 1e-5f) continue;
            float u = cx / cz * (1.f / 704.f);
            float v = cy / cz * (1.f / 256.f);
#pragma unroll
            for (int l = 0; l < 4; l++) {
                int Wl = WS[l], Hl = HS[l];
                float pxf = u * (float)Wl - 0.5f;
                float pyf = v * (float)Hl - 0.5f;
                float fx = floorf(pxf), fy = floorf(pyf);
                int x0 = (int)fx, y0 = (int)fy;
                if (x0 >= Wl || y0 >= Hl || x0 < -1 || y0 < -1) continue;
                float wx = pxf - fx, wy = pyf - fy;
                float g = swl[l];
                int base = OFF[l] + n * Hl * Wl;
                bool xl = (x0 >= 0), xr = (x0 + 1 < Wl);
                bool yt = (y0 >= 0), yb = (y0 + 1 < Hl);
                if (xl && yt) TAP(base + y0 * Wl + x0,           g * (1.f - wx) * (1.f - wy));
                if (xr && yt) TAP(base + y0 * Wl + x0 + 1,       g * wx * (1.f - wy));
                if (xl && yb) TAP(base + (y0 + 1) * Wl + x0,     g * (1.f - wx) * wy);
                if (xr && yb) TAP(base + (y0 + 1) * Wl + x0 + 1, g * wx * wy);
            }
        }
        sOut[pl][lane * 4 + 0] = acc.x;
        sOut[pl][lane * 4 + 1] = acc.y;
        sOut[pl][lane * 4 + 2] = acc.z;
        sOut[pl][lane * 4 + 3] = acc.w;
    }
    __syncthreads();
    for (int j = tid; j < PIX * 64; j += 128) {
        int c = j >> 3;
        int px = (j & 7) * 2;
        uint32_t h, l;
        bfsplit2(sOut[px][c], sOut[px + 1][c], h, l);
        size_t addr = ((size_t)(p * 128 + c)) * HW + pix0 + px;
        *(uint32_t*)(outh + addr) = h;
        *(uint32_t*)(outl + addr) = l;
    }
}

// ---------------- host launch ----------------
static void launch_tgemm(int M, int K, int conv,
                         const uint16_t* Ah, const uint16_t* Al,
                         const uint16_t* Bh, const uint16_t* Bl,
                         float* C, uint16_t* Ch, uint16_t* Cl,
                         const float* bias, const float* residual, int act) {
    static int attr_set = 0;
    if (!attr_set) {
        cudaFuncSetAttribute(tgemm_k, cudaFuncAttributeMaxDynamicSharedMemorySize, TG_DSMEM);
        attr_set = 1;
    }
    tgemm_k<<<dim3(128, M / 128), 256, TG_DSMEM>>>(M, K, conv, Ah, Al, Bh, Bl, C, Ch, Cl, bias, residual, act);
}

extern "C" void kernel_launch(void* const* d_in, const int* in_sizes, int n_in,
                              void* d_out, int out_size) {
    const float* feat[4] = {(const float*)d_in[0], (const float*)d_in[1],
                            (const float*)d_in[2], (const float*)d_in[3]};
    const float* l2i = (const float*)d_in[4];
    const float* bev_query = (const float*)d_in[5];
    const float* bev_pos = (const float*)d_in[6];
    const float* in_w = (const float*)d_in[7];
    const float* in_b = (const float*)d_in[8];
    const float* off_w = (const float*)d_in[9];
    const float* off_b = (const float*)d_in[10];
    const float* sw_w = (const float*)d_in[11];
    const float* sw_b = (const float*)d_in[12];
    const float* pe_w1 = (const float*)d_in[13];
    const float* pe_b1 = (const float*)d_in[14];
    const float* pe_w2 = (const float*)d_in[15];
    const float* pe_b2 = (const float*)d_in[16];
    const float* mid_w1 = (const float*)d_in[17];
    const float* mid_b1 = (const float*)d_in[18];
    const float* mid_w2 = (const float*)d_in[19];
    const float* mid_b2 = (const float*)d_in[20];
    const float* mid_w3 = (const float*)d_in[21];
    const float* mid_b3 = (const float*)d_in[22];
    const float* out_w = (const float*)d_in[23];
    const float* out_b = (const float*)d_in[24];
    float* out = (float*)d_out;

    float *y, *q1, *q2, *ptsb, *swb, *asf, *m1, *m2;
    __half* ftr;
    uint16_t *wsp, *qsp;
    cudaGetSymbolAddress((void**)&ftr, g_ftr);
    cudaGetSymbolAddress((void**)&y, g_y);
    cudaGetSymbolAddress((void**)&q1, g_q1);
    cudaGetSymbolAddress((void**)&q2, g_q2);
    cudaGetSymbolAddress((void**)&ptsb, g_pts);
    cudaGetSymbolAddress((void**)&swb, g_swm);
    cudaGetSymbolAddress((void**)&asf, g_asf);
    cudaGetSymbolAddress((void**)&m1, g_m1);
    cudaGetSymbolAddress((void**)&m2, g_m2);
    cudaGetSymbolAddress((void**)&wsp, g_wsp);
    cudaGetSymbolAddress((void**)&qsp, g_qsp);

    uint16_t* qsph = qsp;                       uint16_t* qspl = qsp + (size_t)3 * QP_PLANE;
    uint16_t* asfh = (uint16_t*)asf;            uint16_t* asfl = asfh + (size_t)1024 * 16384;
    uint16_t* m1h  = (uint16_t*)m1;             uint16_t* m1l  = m1h  + (size_t)512 * 16384;
    uint16_t* m2h  = (uint16_t*)m2;             uint16_t* m2l  = m2h  + (size_t)512 * 16384;
    const size_t WTOT = 1146880;
    uint16_t* w_in_h  = wsp;                    uint16_t* w_in_l  = wsp + WTOT;
    uint16_t* w_m1_h  = wsp + 147456;           uint16_t* w_m1_l  = w_m1_h + WTOT;
    uint16_t* w_m2_h  = wsp + 671744;           uint16_t* w_m2_l  = w_m2_h + WTOT;
    uint16_t* w_m3_h  = wsp + 933888;           uint16_t* w_m3_l  = w_m3_h + WTOT;
    uint16_t* w_out_h = wsp + 999424;           uint16_t* w_out_l = w_out_h + WTOT;

    // 0. pre-split all weights (one launch; conv weights k-permuted)
    wsplit_all_k<<<2240, 256>>>(in_w, mid_w1, mid_w2, mid_w3, out_w, wsp);

    // 1. transpose feats to channel-last fp16 (one launch, all levels)
    transpose_all_k<<<dim3(118, 4, 6), dim3(32, 8)>>>(feat[0], feat[1], feat[2], feat[3], ftr);

    // 2. conv_in (implicit) + residual -> y ; inorm -> q1
    qsplit_k<<<4680, 256>>>(bev_query, qsph, qspl);
    launch_tgemm(128, 1152, 1, w_in_h, w_in_l, qsph, qspl, y, nullptr, nullptr, in_b, bev_query, 0);
    inorm_k<<<128, 256>>>(y, q1);

    // 3. offsets / scale weights / pts / height
    stageB_k<<<256, 256>>>(q1, bev_pos, off_w, off_b, sw_w, sw_b, ptsb, swb, out + 128 * HW);

    // 4. sampling + PE -> asf bf16 planes
    sample_k<<<dim3(1024, 8), 128>>>(ptsb, swb, l2i, pe_w1, pe_b1, pe_w2, pe_b2, asfh, asfl);

    // 5. mid MLP chain
    launch_tgemm(512, 1024, 0, w_m1_h, w_m1_l, asfh, asfl, nullptr, m1h, m1l, mid_b1, nullptr, 1);
    launch_tgemm(512,  512, 0, w_m2_h, w_m2_l, m1h,  m1l,  nullptr, m2h, m2l, mid_b2, nullptr, 1);
    launch_tgemm(128,  512, 0, w_m3_h, w_m3_l, m2h,  m2l,  y, nullptr, nullptr, mid_b3, q1, 0);
    inorm_k<<<128, 256>>>(y, q2);

    // 6. conv_out (implicit) + residual ; final inorm -> d_out (q)
    qsplit_k<<<4680, 256>>>(q2, qsph, qspl);
    launch_tgemm(128, 1152, 1, w_out_h, w_out_l, qsph, qspl, y, nullptr, nullptr, out_b, q2, 0);
    inorm_k<<<128, 256>>>(y, out);
}